// round 6
// baseline (speedup 1.0000x reference)
#include <cuda_runtime.h>
#include <cuda_bf16.h>
#include <cstdint>
#include <math.h>

#define BZ   2
#define SQ   2048
#define DM   1024
#define HH   16
#define HD   64
#define MR   (BZ*SQ)      // 4096 rows
#define K3   (3*DM)       // 3072 expanded-K

// ---- device-global scratch (no allocations allowed) ----
__device__ float g_q[(size_t)MR*DM];
__device__ float g_k[(size_t)MR*DM];
__device__ float g_v[(size_t)MR*DM];
__device__ float g_o[(size_t)MR*DM];
__device__ __nv_bfloat16 g_x3[(size_t)MR*K3];
__device__ __nv_bfloat16 g_o3[(size_t)MR*K3];
__device__ __nv_bfloat16 g_wq3[(size_t)K3*DM];
__device__ __nv_bfloat16 g_wk3[(size_t)K3*DM];
__device__ __nv_bfloat16 g_wv3[(size_t)K3*DM];
__device__ __nv_bfloat16 g_wo3[(size_t)K3*DM];

// ---------------------------------------------------------------------------
// Split-expansion: hi = bf16(x), lo = bf16(x - hi)
// A3 = [Ah | Ah | Al] (row-wise), B3 = [Bh ; Bl ; Bh] (k-wise)
// => A3 @ B3 = Ah*Bh + Ah*Bl + Al*Bh  (fp32-class accuracy)
// ---------------------------------------------------------------------------
__global__ __launch_bounds__(256) void expand_a3(
    const float* __restrict__ src, __nv_bfloat16* __restrict__ dst, int M, int K)
{
    int idx = blockIdx.x*256 + threadIdx.x;
    if (idx >= M*K) return;
    int m = idx / K, k = idx - m*K;
    float x = src[idx];
    __nv_bfloat16 h = __float2bfloat16(x);
    __nv_bfloat16 l = __float2bfloat16(x - __bfloat162float(h));
    size_t base = (size_t)m*3*K;
    dst[base + k] = h;
    dst[base + K + k] = h;
    dst[base + 2*K + k] = l;
}

__global__ __launch_bounds__(256) void expand_b3(
    const float* __restrict__ src, __nv_bfloat16* __restrict__ dst, int K, int N)
{
    int idx = blockIdx.x*256 + threadIdx.x;
    if (idx >= K*N) return;
    int k = idx / N, n = idx - k*N;
    float x = src[idx];
    __nv_bfloat16 h = __float2bfloat16(x);
    __nv_bfloat16 l = __float2bfloat16(x - __bfloat162float(h));
    dst[(size_t)k*N + n]         = h;
    dst[(size_t)(K+k)*N + n]     = l;
    dst[(size_t)(2*K+k)*N + n]   = h;
}

// ---------------------------------------------------------------------------
// bf16 tensor-core GEMM v2: C[M,N] = A3[M,Kx] @ B3[Kx,N] + bias
// 128x128 block tile, BK=32, 256 thr (8 warps 2x4), warp tile 64x32.
// cp.async double-buffer, ldmatrix(.trans) fragments, mma m16n8k16.
// A smem: [128 rows][32 bf16], row stride 80B (pad -> conflict-free LDSM).
// B smem: [32 k][128 n], row stride 256B, chunk^(k&7) swizzle.
// ---------------------------------------------------------------------------
#define A_STRIDE 80          // bytes per A smem row (64 data + 16 pad)
#define A_STAGE  (128*A_STRIDE)   // 10240 B
#define B_STAGE  (32*256)         // 8192 B

__global__ __launch_bounds__(256) void gemm_bf16(
    const __nv_bfloat16* __restrict__ A, const __nv_bfloat16* __restrict__ B,
    const float* __restrict__ bias, float* __restrict__ C,
    int M, int N, int Kx)
{
    __shared__ __align__(16) uint8_t smA[2*A_STAGE];  // 20 KB
    __shared__ __align__(16) uint8_t smB[2*B_STAGE];  // 16 KB

    const int tid  = threadIdx.x;
    const int lane = tid & 31;
    const int w    = tid >> 5;
    const int wm   = w >> 2;         // 0..1
    const int wn   = w & 3;          // 0..3
    const int m0 = blockIdx.y * 128;
    const int n0 = blockIdx.x * 128;

    uint32_t sA = (uint32_t)__cvta_generic_to_shared(smA);
    uint32_t sB = (uint32_t)__cvta_generic_to_shared(smB);

    // cp.async source/dest precompute
    // A: 512 16B-chunks/stage: row = idx>>2 (0..127), ch = idx&3
    // B: 512 16B-chunks/stage: k = idx>>4 (0..31), ch = idx&15
    int a_row0 = tid >> 2,          a_ch0 = tid & 3;
    int a_row1 = (tid + 256) >> 2,  a_ch1 = (tid + 256) & 3;
    int b_k0   = tid >> 4,          b_ch0 = tid & 15;
    int b_k1   = (tid + 256) >> 4,  b_ch1 = (tid + 256) & 15;

    const __nv_bfloat16* gA0 = A + (size_t)(m0 + a_row0)*Kx + a_ch0*8;
    const __nv_bfloat16* gA1 = A + (size_t)(m0 + a_row1)*Kx + a_ch1*8;
    const __nv_bfloat16* gB0 = B + (size_t)b_k0*N + n0 + b_ch0*8;
    const __nv_bfloat16* gB1 = B + (size_t)b_k1*N + n0 + b_ch1*8;

    uint32_t dA0 = sA + a_row0*A_STRIDE + a_ch0*16;
    uint32_t dA1 = sA + a_row1*A_STRIDE + a_ch1*16;
    uint32_t dB0 = sB + b_k0*256 + ((b_ch0 ^ (b_k0 & 7))*16);
    uint32_t dB1 = sB + b_k1*256 + ((b_ch1 ^ (b_k1 & 7))*16);

    float acc[4][4][4];
    #pragma unroll
    for (int i = 0; i < 4; i++)
        #pragma unroll
        for (int j = 0; j < 4; j++)
            #pragma unroll
            for (int r = 0; r < 4; r++) acc[i][j][r] = 0.f;

    const int NC = Kx >> 5;   // chunks of 32

    // prefetch chunk 0 into stage 0
    {
        asm volatile("cp.async.cg.shared.global [%0], [%1], 16;\n" :: "r"(dA0), "l"(gA0));
        asm volatile("cp.async.cg.shared.global [%0], [%1], 16;\n" :: "r"(dA1), "l"(gA1));
        asm volatile("cp.async.cg.shared.global [%0], [%1], 16;\n" :: "r"(dB0), "l"(gB0));
        asm volatile("cp.async.cg.shared.global [%0], [%1], 16;\n" :: "r"(dB1), "l"(gB1));
        asm volatile("cp.async.commit_group;\n");
    }

    // ldmatrix lane decomposition
    const int sub = lane >> 3;       // 0..3
    const int r8  = lane & 7;

    for (int c = 0; c < NC; c++) {
        int s  = c & 1;
        int sn = s ^ 1;
        if (c + 1 < NC) {
            int koff = (c + 1) << 5;
            asm volatile("cp.async.cg.shared.global [%0], [%1], 16;\n"
                         :: "r"(dA0 + sn*A_STAGE), "l"(gA0 + koff));
            asm volatile("cp.async.cg.shared.global [%0], [%1], 16;\n"
                         :: "r"(dA1 + sn*A_STAGE), "l"(gA1 + koff));
            asm volatile("cp.async.cg.shared.global [%0], [%1], 16;\n"
                         :: "r"(dB0 + sn*B_STAGE), "l"(gB0 + (size_t)koff*N));
            asm volatile("cp.async.cg.shared.global [%0], [%1], 16;\n"
                         :: "r"(dB1 + sn*B_STAGE), "l"(gB1 + (size_t)koff*N));
            asm volatile("cp.async.commit_group;\n");
            asm volatile("cp.async.wait_group 1;\n");
        } else {
            asm volatile("cp.async.wait_group 0;\n");
        }
        __syncthreads();

        uint32_t baseA = sA + s*A_STAGE;
        uint32_t baseB = sB + s*B_STAGE;

        #pragma unroll
        for (int kk = 0; kk < 2; kk++) {
            // A fragments: 4 m-tiles of 16 rows
            uint32_t a[4][4];
            #pragma unroll
            for (int mt = 0; mt < 4; mt++) {
                int row = wm*64 + mt*16 + (sub & 1)*8 + r8;
                int ch  = kk*2 + (sub >> 1);
                uint32_t addr = baseA + row*A_STRIDE + ch*16;
                asm volatile("ldmatrix.sync.aligned.m8n8.x4.shared.b16 {%0,%1,%2,%3}, [%4];"
                             : "=r"(a[mt][0]), "=r"(a[mt][1]), "=r"(a[mt][2]), "=r"(a[mt][3])
                             : "r"(addr));
            }
            // B fragments: 2 trans-x4 loads cover n = wn*32 .. +31
            uint32_t b[4][2];
            #pragma unroll
            for (int pair = 0; pair < 2; pair++) {
                int k   = kk*16 + (sub & 1)*8 + r8;
                int nch = wn*4 + pair*2 + (sub >> 1);
                uint32_t addr = baseB + k*256 + ((nch ^ (k & 7))*16);
                uint32_t r0, r1, r2, r3;
                asm volatile("ldmatrix.sync.aligned.m8n8.x4.trans.shared.b16 {%0,%1,%2,%3}, [%4];"
                             : "=r"(r0), "=r"(r1), "=r"(r2), "=r"(r3)
                             : "r"(addr));
                b[pair*2][0]   = r0; b[pair*2][1]   = r1;
                b[pair*2+1][0] = r2; b[pair*2+1][1] = r3;
            }
            #pragma unroll
            for (int mt = 0; mt < 4; mt++)
                #pragma unroll
                for (int nt = 0; nt < 4; nt++) {
                    asm volatile(
                        "mma.sync.aligned.m16n8k16.row.col.f32.bf16.bf16.f32 "
                        "{%0,%1,%2,%3}, {%4,%5,%6,%7}, {%8,%9}, {%0,%1,%2,%3};"
                        : "+f"(acc[mt][nt][0]), "+f"(acc[mt][nt][1]),
                          "+f"(acc[mt][nt][2]), "+f"(acc[mt][nt][3])
                        : "r"(a[mt][0]), "r"(a[mt][1]), "r"(a[mt][2]), "r"(a[mt][3]),
                          "r"(b[nt][0]), "r"(b[nt][1]));
                }
        }
        __syncthreads();
    }

    // Epilogue: bias add, fp32 store
    const int g = lane >> 2;
    const int t = lane & 3;
    #pragma unroll
    for (int mt = 0; mt < 4; mt++) {
        int row0 = m0 + wm*64 + mt*16 + g;
        #pragma unroll
        for (int nt = 0; nt < 4; nt++) {
            int col = n0 + wn*32 + nt*8 + 2*t;
            float b0 = bias[col], b1 = bias[col+1];
            C[(size_t)row0*N + col]         = acc[mt][nt][0] + b0;
            C[(size_t)row0*N + col + 1]     = acc[mt][nt][1] + b1;
            C[(size_t)(row0+8)*N + col]     = acc[mt][nt][2] + b0;
            C[(size_t)(row0+8)*N + col + 1] = acc[mt][nt][3] + b1;
        }
    }
}

// ---------------------------------------------------------------------------
// Flash attention (fp32 SIMT, unchanged): one block per (64 q-rows, head,
// batch), k-tiles of 32, static smem < 48KB.
// ---------------------------------------------------------------------------
#define PST 68
#define PSS 36

__global__ __launch_bounds__(256) void attn_kernel()
{
    __shared__ float Qs[64*PST];
    __shared__ float Ks[32*PST];
    __shared__ float Vs[32*PST];
    __shared__ float Ps[64*PSS];
    __shared__ float mrow[64], lrow[64], arow[64];

    int tid = threadIdx.x;
    int q0 = blockIdx.x * 64;
    int h  = blockIdx.y;
    int b  = blockIdx.z;
    const float scale = 0.125f;

    int sx = tid & 7;
    int sy = tid >> 3;
    int ox = tid & 15;
    int oy = tid >> 4;

    const float* Qg = g_q + (size_t)(b*SQ + q0)*DM + h*HD;
    #pragma unroll
    for (int i = 0; i < 4; i++) {
        int idx4 = tid + i*256;
        int r = idx4 >> 4, c4 = idx4 & 15;
        float4 v = *(const float4*)(Qg + (size_t)r*DM + c4*4);
        v.x *= scale; v.y *= scale; v.z *= scale; v.w *= scale;
        *(float4*)&Qs[r*PST + c4*4] = v;
    }
    if (tid < 64) { mrow[tid] = -INFINITY; lrow[tid] = 0.f; }

    float o[4][4] = {};
    __syncthreads();

    for (int k0 = 0; k0 < SQ; k0 += 32) {
        const float* Kg = g_k + (size_t)(b*SQ + k0)*DM + h*HD;
        const float* Vg = g_v + (size_t)(b*SQ + k0)*DM + h*HD;
        #pragma unroll
        for (int i = 0; i < 2; i++) {
            int idx4 = tid + i*256;
            int r = idx4 >> 4, c4 = idx4 & 15;
            *(float4*)&Ks[r*PST + c4*4] = *(const float4*)(Kg + (size_t)r*DM + c4*4);
            *(float4*)&Vs[r*PST + c4*4] = *(const float4*)(Vg + (size_t)r*DM + c4*4);
        }
        __syncthreads();

        float s[2][4] = {};
        #pragma unroll 16
        for (int d = 0; d < 64; d++) {
            float qv[2], kv[4];
            qv[0] = Qs[sy*PST + d];
            qv[1] = Qs[(sy+32)*PST + d];
            #pragma unroll
            for (int j = 0; j < 4; j++) kv[j] = Ks[(sx*4+j)*PST + d];
            #pragma unroll
            for (int i = 0; i < 2; i++)
                #pragma unroll
                for (int j = 0; j < 4; j++)
                    s[i][j] = fmaf(qv[i], kv[j], s[i][j]);
        }
        #pragma unroll
        for (int i = 0; i < 2; i++) {
            int q = sy + 32*i;
            *(float4*)&Ps[q*PSS + sx*4] = make_float4(s[i][0], s[i][1], s[i][2], s[i][3]);
        }
        __syncthreads();

        if (tid < 64) {
            int q = tid;
            float mo = mrow[q];
            float mx = mo;
            #pragma unroll 8
            for (int j = 0; j < 32; j++) mx = fmaxf(mx, Ps[q*PSS + j]);
            float sum = 0.f;
            #pragma unroll 8
            for (int j = 0; j < 32; j++) {
                float p = __expf(Ps[q*PSS + j] - mx);
                Ps[q*PSS + j] = p;
                sum += p;
            }
            float al = __expf(mo - mx);
            lrow[q] = lrow[q]*al + sum;
            mrow[q] = mx;
            arow[q] = al;
        }
        __syncthreads();

        float al[4];
        #pragma unroll
        for (int i = 0; i < 4; i++) al[i] = arow[oy + 16*i];
        #pragma unroll
        for (int i = 0; i < 4; i++)
            #pragma unroll
            for (int j = 0; j < 4; j++)
                o[i][j] *= al[i];

        #pragma unroll 8
        for (int kk = 0; kk < 32; kk++) {
            float pv[4], vv[4];
            #pragma unroll
            for (int i = 0; i < 4; i++) pv[i] = Ps[(oy + 16*i)*PSS + kk];
            #pragma unroll
            for (int j = 0; j < 4; j++) vv[j] = Vs[kk*PST + ox*4 + j];
            #pragma unroll
            for (int i = 0; i < 4; i++)
                #pragma unroll
                for (int j = 0; j < 4; j++)
                    o[i][j] = fmaf(pv[i], vv[j], o[i][j]);
        }
        __syncthreads();
    }

    float* Og = g_o + (size_t)(b*SQ + q0)*DM + h*HD;
    #pragma unroll
    for (int i = 0; i < 4; i++) {
        int q = oy + 16*i;
        float inv = 1.f / lrow[q];
        #pragma unroll
        for (int j = 0; j < 4; j++)
            Og[(size_t)q*DM + ox*4 + j] = o[i][j] * inv;
    }
}

extern "C" void kernel_launch(void* const* d_in, const int* in_sizes, int n_in,
                              void* d_out, int out_size)
{
    const float* x  = (const float*)d_in[0];
    const float* wq = (const float*)d_in[1];
    const float* bq = (const float*)d_in[2];
    const float* wk = (const float*)d_in[3];
    const float* bk = (const float*)d_in[4];
    const float* wv = (const float*)d_in[5];
    const float* bv = (const float*)d_in[6];
    const float* wo = (const float*)d_in[7];
    const float* bo = (const float*)d_in[8];
    float* out = (float*)d_out;

    float *q, *k, *v, *o;
    __nv_bfloat16 *x3, *o3, *wq3, *wk3, *wv3, *wo3;
    cudaGetSymbolAddress((void**)&q, g_q);
    cudaGetSymbolAddress((void**)&k, g_k);
    cudaGetSymbolAddress((void**)&v, g_v);
    cudaGetSymbolAddress((void**)&o, g_o);
    cudaGetSymbolAddress((void**)&x3, g_x3);
    cudaGetSymbolAddress((void**)&o3, g_o3);
    cudaGetSymbolAddress((void**)&wq3, g_wq3);
    cudaGetSymbolAddress((void**)&wk3, g_wk3);
    cudaGetSymbolAddress((void**)&wv3, g_wv3);
    cudaGetSymbolAddress((void**)&wo3, g_wo3);

    int eb = (MR*DM + 255)/256;
    int wb = (DM*DM + 255)/256;

    expand_a3<<<eb, 256>>>(x, x3, MR, DM);
    expand_b3<<<wb, 256>>>(wq, wq3, DM, DM);
    expand_b3<<<wb, 256>>>(wk, wk3, DM, DM);
    expand_b3<<<wb, 256>>>(wv, wv3, DM, DM);
    expand_b3<<<wb, 256>>>(wo, wo3, DM, DM);

    dim3 gg(DM/128, MR/128);        // (8, 32)
    gemm_bf16<<<gg, 256>>>(x3, wq3, bq, q, MR, DM, K3);
    gemm_bf16<<<gg, 256>>>(x3, wk3, bk, k, MR, DM, K3);
    gemm_bf16<<<gg, 256>>>(x3, wv3, bv, v, MR, DM, K3);

    attn_kernel<<<dim3(SQ/64, HH, BZ), 256>>>();

    expand_a3<<<eb, 256>>>(o, o3, MR, DM);
    gemm_bf16<<<gg, 256>>>(o3, wo3, bo, out, MR, DM, K3);
}

// round 9
// speedup vs baseline: 1.1039x; 1.1039x over previous
#include <cuda_runtime.h>
#include <cuda_bf16.h>
#include <cstdint>
#include <math.h>

#define BZ   2
#define SQ   2048
#define DM   1024
#define HH   16
#define HD   64
#define MR   (BZ*SQ)      // 4096 rows
#define K3   (3*DM)       // 3072 expanded-K

// ---- device-global scratch (no allocations allowed) ----
__device__ float g_q[(size_t)MR*DM];
__device__ float g_k[(size_t)MR*DM];
__device__ float g_v[(size_t)MR*DM];
__device__ float g_o[(size_t)MR*DM];
__device__ __align__(16) __nv_bfloat16 g_x3[(size_t)MR*K3];
__device__ __align__(16) __nv_bfloat16 g_o3[(size_t)MR*K3];
__device__ __align__(16) __nv_bfloat16 g_wq3[(size_t)DM*K3];   // transposed: [N][K3]
__device__ __align__(16) __nv_bfloat16 g_wk3[(size_t)DM*K3];
__device__ __align__(16) __nv_bfloat16 g_wv3[(size_t)DM*K3];
__device__ __align__(16) __nv_bfloat16 g_wo3[(size_t)DM*K3];

// ---------------------------------------------------------------------------
// Split-expansion: hi = bf16(x), lo = bf16(x - hi)
// A3[m][0:K]=h, [K:2K]=h, [2K:3K]=l    (row-major [M][3K])
// B3t[n][0:K]=h, [K:2K]=l, [2K:3K]=h   (TRANSPOSED  [N][3K], K-major)
// => sum over 3K of A3[m][k']*B3t[n][k'] = Ah*Bh + Ah*Bl + Al*Bh
// ---------------------------------------------------------------------------
__global__ __launch_bounds__(256) void expand_a3(
    const float* __restrict__ src, __nv_bfloat16* __restrict__ dst, int M, int K)
{
    int idx = blockIdx.x*256 + threadIdx.x;
    if (idx >= M*K) return;
    int m = idx / K, k = idx - m*K;
    float x = src[idx];
    __nv_bfloat16 h = __float2bfloat16(x);
    __nv_bfloat16 l = __float2bfloat16(x - __bfloat162float(h));
    size_t base = (size_t)m*3*K;
    dst[base + k] = h;
    dst[base + K + k] = h;
    dst[base + 2*K + k] = l;
}

// transpose-expand: src [K][N] -> dst [N][3K] with blocks [h | l | h]
__global__ __launch_bounds__(256) void expand_b3t(
    const float* __restrict__ src, __nv_bfloat16* __restrict__ dst, int K, int N)
{
    __shared__ float t[32][33];
    int tx = threadIdx.x & 31, ty = threadIdx.x >> 5;   // 32 x 8
    int nb = blockIdx.x * 32, kb = blockIdx.y * 32;
    #pragma unroll
    for (int i = 0; i < 4; i++)
        t[ty + 8*i][tx] = src[(size_t)(kb + ty + 8*i)*N + nb + tx];
    __syncthreads();
    #pragma unroll
    for (int i = 0; i < 4; i++) {
        int n = nb + ty + 8*i;
        int k = kb + tx;
        float x = t[tx][ty + 8*i];   // src[k][n]
        __nv_bfloat16 h = __float2bfloat16(x);
        __nv_bfloat16 l = __float2bfloat16(x - __bfloat162float(h));
        size_t base = (size_t)n*3*K;
        dst[base + k]       = h;
        dst[base + K + k]   = l;
        dst[base + 2*K + k] = h;
    }
}

// ---------------------------------------------------------------------------
// bf16 HMMA GEMM v3b: C[M,N] = A3[M,Kx] @ B3t[N,Kx]^T + bias
// 128x128 block tile, BK=32, 256 thr (8 warps 2x4), warp tile 64x32.
// Both operands K-major [row][32 bf16] -> identical uint4 tile loads,
// double-buffered smem (1 sync/chunk), register prefetch of next chunk.
// Row stride 20 u32 (16 data + 4 pad): uint4 slots 16B-aligned AND fragment
// LDS conflict-free (banks 20g+t mod 32 all distinct across the warp).
// ---------------------------------------------------------------------------
#define AST 20                    // u32 stride per 32-bf16 row
#define STG (128*AST)             // u32 per stage (10240 B)

__global__ __launch_bounds__(256, 2) void gemm_bf16(
    const __nv_bfloat16* __restrict__ A, const __nv_bfloat16* __restrict__ Bt,
    const float* __restrict__ bias, float* __restrict__ C,
    int M, int N, int Kx)
{
    __shared__ __align__(16) uint32_t As[2*STG];   // 20 KB
    __shared__ __align__(16) uint32_t Bs[2*STG];   // 20 KB

    const int tid  = threadIdx.x;
    const int lane = tid & 31;
    const int w    = tid >> 5;
    const int wm   = w >> 2;         // 0..1
    const int wn   = w & 3;          // 0..3
    const int g    = lane >> 2;      // 0..7
    const int t    = lane & 3;       // 0..3
    const int m0 = blockIdx.y * 128;
    const int n0 = blockIdx.x * 128;

    // tile-load mapping: 512 uint4 per operand per chunk; 2 per thread
    const int r0 = tid >> 2,         c0 = tid & 3;
    const int r1 = (tid + 256) >> 2, c1 = (tid + 256) & 3;

    const __nv_bfloat16* pA0 = A  + (size_t)(m0 + r0)*Kx + c0*8;
    const __nv_bfloat16* pA1 = A  + (size_t)(m0 + r1)*Kx + c1*8;
    const __nv_bfloat16* pB0 = Bt + (size_t)(n0 + r0)*Kx + c0*8;
    const __nv_bfloat16* pB1 = Bt + (size_t)(n0 + r1)*Kx + c1*8;

    float acc[4][4][4];
    #pragma unroll
    for (int i = 0; i < 4; i++)
        #pragma unroll
        for (int j = 0; j < 4; j++)
            #pragma unroll
            for (int r = 0; r < 4; r++) acc[i][j][r] = 0.f;

    const int NC = Kx >> 5;          // 96 chunks of 32

    // prologue: chunk 0 -> stage 0
    {
        uint4 ra0 = *(const uint4*)pA0;
        uint4 ra1 = *(const uint4*)pA1;
        uint4 rb0 = *(const uint4*)pB0;
        uint4 rb1 = *(const uint4*)pB1;
        *(uint4*)&As[r0*AST + c0*4] = ra0;
        *(uint4*)&As[r1*AST + c1*4] = ra1;
        *(uint4*)&Bs[r0*AST + c0*4] = rb0;
        *(uint4*)&Bs[r1*AST + c1*4] = rb1;
    }

    for (int c = 0; c < NC; c++) {
        __syncthreads();             // stage (c&1) is ready
        const int s = c & 1;
        const int sn = s ^ 1;

        uint4 ra0, ra1, rb0, rb1;
        const bool pf = (c + 1 < NC);
        if (pf) {
            int ko = (c + 1) << 5;
            ra0 = *(const uint4*)(pA0 + ko);
            ra1 = *(const uint4*)(pA1 + ko);
            rb0 = *(const uint4*)(pB0 + ko);
            rb1 = *(const uint4*)(pB1 + ko);
        }

        const uint32_t* Ab = As + s*STG;
        const uint32_t* Bb = Bs + s*STG;

        #pragma unroll
        for (int kk = 0; kk < 2; kk++) {
            uint32_t a[4][4], b[4][2];
            #pragma unroll
            for (int mt = 0; mt < 4; mt++) {
                int ar = (wm*64 + mt*16 + g)*AST + kk*8 + t;
                a[mt][0] = Ab[ar];
                a[mt][1] = Ab[ar + 8*AST];
                a[mt][2] = Ab[ar + 4];
                a[mt][3] = Ab[ar + 8*AST + 4];
            }
            #pragma unroll
            for (int nt = 0; nt < 4; nt++) {
                int br = (wn*32 + nt*8 + g)*AST + kk*8 + t;
                b[nt][0] = Bb[br];
                b[nt][1] = Bb[br + 4];
            }
            #pragma unroll
            for (int mt = 0; mt < 4; mt++)
                #pragma unroll
                for (int nt = 0; nt < 4; nt++) {
                    asm volatile(
                        "mma.sync.aligned.m16n8k16.row.col.f32.bf16.bf16.f32 "
                        "{%0,%1,%2,%3}, {%4,%5,%6,%7}, {%8,%9}, {%0,%1,%2,%3};"
                        : "+f"(acc[mt][nt][0]), "+f"(acc[mt][nt][1]),
                          "+f"(acc[mt][nt][2]), "+f"(acc[mt][nt][3])
                        : "r"(a[mt][0]), "r"(a[mt][1]), "r"(a[mt][2]), "r"(a[mt][3]),
                          "r"(b[nt][0]), "r"(b[nt][1]));
                }
        }

        if (pf) {
            *(uint4*)&As[sn*STG + r0*AST + c0*4] = ra0;
            *(uint4*)&As[sn*STG + r1*AST + c1*4] = ra1;
            *(uint4*)&Bs[sn*STG + r0*AST + c0*4] = rb0;
            *(uint4*)&Bs[sn*STG + r1*AST + c1*4] = rb1;
        }
    }

    // Epilogue: bias add, fp32 store
    #pragma unroll
    for (int mt = 0; mt < 4; mt++) {
        int row0 = m0 + wm*64 + mt*16 + g;
        #pragma unroll
        for (int nt = 0; nt < 4; nt++) {
            int col = n0 + wn*32 + nt*8 + 2*t;
            float b0 = bias[col], b1 = bias[col+1];
            C[(size_t)row0*N + col]         = acc[mt][nt][0] + b0;
            C[(size_t)row0*N + col + 1]     = acc[mt][nt][1] + b1;
            C[(size_t)(row0+8)*N + col]     = acc[mt][nt][2] + b0;
            C[(size_t)(row0+8)*N + col + 1] = acc[mt][nt][3] + b1;
        }
    }
}

// ---------------------------------------------------------------------------
// Flash attention (fp32 SIMT, unchanged): one block per (64 q-rows, head,
// batch), k-tiles of 32, static smem < 48KB.
// ---------------------------------------------------------------------------
#define PST 68
#define PSS 36

__global__ __launch_bounds__(256) void attn_kernel()
{
    __shared__ float Qs[64*PST];
    __shared__ float Ks[32*PST];
    __shared__ float Vs[32*PST];
    __shared__ float Ps[64*PSS];
    __shared__ float mrow[64], lrow[64], arow[64];

    int tid = threadIdx.x;
    int q0 = blockIdx.x * 64;
    int h  = blockIdx.y;
    int b  = blockIdx.z;
    const float scale = 0.125f;

    int sx = tid & 7;
    int sy = tid >> 3;
    int ox = tid & 15;
    int oy = tid >> 4;

    const float* Qg = g_q + (size_t)(b*SQ + q0)*DM + h*HD;
    #pragma unroll
    for (int i = 0; i < 4; i++) {
        int idx4 = tid + i*256;
        int r = idx4 >> 4, c4 = idx4 & 15;
        float4 v = *(const float4*)(Qg + (size_t)r*DM + c4*4);
        v.x *= scale; v.y *= scale; v.z *= scale; v.w *= scale;
        *(float4*)&Qs[r*PST + c4*4] = v;
    }
    if (tid < 64) { mrow[tid] = -INFINITY; lrow[tid] = 0.f; }

    float o[4][4] = {};
    __syncthreads();

    for (int k0 = 0; k0 < SQ; k0 += 32) {
        const float* Kg = g_k + (size_t)(b*SQ + k0)*DM + h*HD;
        const float* Vg = g_v + (size_t)(b*SQ + k0)*DM + h*HD;
        #pragma unroll
        for (int i = 0; i < 2; i++) {
            int idx4 = tid + i*256;
            int r = idx4 >> 4, c4 = idx4 & 15;
            *(float4*)&Ks[r*PST + c4*4] = *(const float4*)(Kg + (size_t)r*DM + c4*4);
            *(float4*)&Vs[r*PST + c4*4] = *(const float4*)(Vg + (size_t)r*DM + c4*4);
        }
        __syncthreads();

        float s[2][4] = {};
        #pragma unroll 16
        for (int d = 0; d < 64; d++) {
            float qv[2], kv[4];
            qv[0] = Qs[sy*PST + d];
            qv[1] = Qs[(sy+32)*PST + d];
            #pragma unroll
            for (int j = 0; j < 4; j++) kv[j] = Ks[(sx*4+j)*PST + d];
            #pragma unroll
            for (int i = 0; i < 2; i++)
                #pragma unroll
                for (int j = 0; j < 4; j++)
                    s[i][j] = fmaf(qv[i], kv[j], s[i][j]);
        }
        #pragma unroll
        for (int i = 0; i < 2; i++) {
            int q = sy + 32*i;
            *(float4*)&Ps[q*PSS + sx*4] = make_float4(s[i][0], s[i][1], s[i][2], s[i][3]);
        }
        __syncthreads();

        if (tid < 64) {
            int q = tid;
            float mo = mrow[q];
            float mx = mo;
            #pragma unroll 8
            for (int j = 0; j < 32; j++) mx = fmaxf(mx, Ps[q*PSS + j]);
            float sum = 0.f;
            #pragma unroll 8
            for (int j = 0; j < 32; j++) {
                float p = __expf(Ps[q*PSS + j] - mx);
                Ps[q*PSS + j] = p;
                sum += p;
            }
            float al = __expf(mo - mx);
            lrow[q] = lrow[q]*al + sum;
            mrow[q] = mx;
            arow[q] = al;
        }
        __syncthreads();

        float al[4];
        #pragma unroll
        for (int i = 0; i < 4; i++) al[i] = arow[oy + 16*i];
        #pragma unroll
        for (int i = 0; i < 4; i++)
            #pragma unroll
            for (int j = 0; j < 4; j++)
                o[i][j] *= al[i];

        #pragma unroll 8
        for (int kk = 0; kk < 32; kk++) {
            float pv[4], vv[4];
            #pragma unroll
            for (int i = 0; i < 4; i++) pv[i] = Ps[(oy + 16*i)*PSS + kk];
            #pragma unroll
            for (int j = 0; j < 4; j++) vv[j] = Vs[kk*PST + ox*4 + j];
            #pragma unroll
            for (int i = 0; i < 4; i++)
                #pragma unroll
                for (int j = 0; j < 4; j++)
                    o[i][j] = fmaf(pv[i], vv[j], o[i][j]);
        }
        __syncthreads();
    }

    float* Og = g_o + (size_t)(b*SQ + q0)*DM + h*HD;
    #pragma unroll
    for (int i = 0; i < 4; i++) {
        int q = oy + 16*i;
        float inv = 1.f / lrow[q];
        #pragma unroll
        for (int j = 0; j < 4; j++)
            Og[(size_t)q*DM + ox*4 + j] = o[i][j] * inv;
    }
}

extern "C" void kernel_launch(void* const* d_in, const int* in_sizes, int n_in,
                              void* d_out, int out_size)
{
    const float* x  = (const float*)d_in[0];
    const float* wq = (const float*)d_in[1];
    const float* bq = (const float*)d_in[2];
    const float* wk = (const float*)d_in[3];
    const float* bk = (const float*)d_in[4];
    const float* wv = (const float*)d_in[5];
    const float* bv = (const float*)d_in[6];
    const float* wo = (const float*)d_in[7];
    const float* bo = (const float*)d_in[8];
    float* out = (float*)d_out;

    float *q, *k, *v, *o;
    __nv_bfloat16 *x3, *o3, *wq3, *wk3, *wv3, *wo3;
    cudaGetSymbolAddress((void**)&q, g_q);
    cudaGetSymbolAddress((void**)&k, g_k);
    cudaGetSymbolAddress((void**)&v, g_v);
    cudaGetSymbolAddress((void**)&o, g_o);
    cudaGetSymbolAddress((void**)&x3, g_x3);
    cudaGetSymbolAddress((void**)&o3, g_o3);
    cudaGetSymbolAddress((void**)&wq3, g_wq3);
    cudaGetSymbolAddress((void**)&wk3, g_wk3);
    cudaGetSymbolAddress((void**)&wv3, g_wv3);
    cudaGetSymbolAddress((void**)&wo3, g_wo3);

    int eb = (MR*DM + 255)/256;
    dim3 tb(DM/32, DM/32);          // 32x32 transpose tiles

    expand_a3<<<eb, 256>>>(x, x3, MR, DM);
    expand_b3t<<<tb, 256>>>(wq, wq3, DM, DM);
    expand_b3t<<<tb, 256>>>(wk, wk3, DM, DM);
    expand_b3t<<<tb, 256>>>(wv, wv3, DM, DM);
    expand_b3t<<<tb, 256>>>(wo, wo3, DM, DM);

    dim3 gg(DM/128, MR/128);        // (8, 32)
    gemm_bf16<<<gg, 256>>>(x3, wq3, bq, q, MR, DM, K3);
    gemm_bf16<<<gg, 256>>>(x3, wk3, bk, k, MR, DM, K3);
    gemm_bf16<<<gg, 256>>>(x3, wv3, bv, v, MR, DM, K3);

    attn_kernel<<<dim3(SQ/64, HH, BZ), 256>>>();

    expand_a3<<<eb, 256>>>(o, o3, MR, DM);
    gemm_bf16<<<gg, 256>>>(o3, wo3, bo, out, MR, DM, K3);
}

// round 10
// speedup vs baseline: 1.6691x; 1.5119x over previous
#include <cuda_runtime.h>
#include <cuda_bf16.h>
#include <cstdint>
#include <math.h>

#define BZ   2
#define SQ   2048
#define DM   1024
#define HH   16
#define HD   64
#define MR   (BZ*SQ)      // 4096 rows
#define K3   (3*DM)       // 3072 expanded-K

// ---- device-global scratch (no allocations allowed) ----
__device__ float g_q[(size_t)MR*DM];
__device__ float g_k[(size_t)MR*DM];
__device__ float g_v[(size_t)MR*DM];
__device__ float g_o[(size_t)MR*DM];
__device__ __align__(16) __nv_bfloat16 g_x3[(size_t)MR*K3];
__device__ __align__(16) __nv_bfloat16 g_o3[(size_t)MR*K3];
__device__ __align__(16) __nv_bfloat16 g_wq3[(size_t)K3*DM];   // row-major [K3][N]
__device__ __align__(16) __nv_bfloat16 g_wk3[(size_t)K3*DM];
__device__ __align__(16) __nv_bfloat16 g_wv3[(size_t)K3*DM];
__device__ __align__(16) __nv_bfloat16 g_wo3[(size_t)K3*DM];

// ---------------------------------------------------------------------------
// Split-expansion kernels (R3-exact): hi = bf16(x), lo = bf16(x - hi)
// A3[m, 0:K]=hi, A3[m, K:2K]=hi, A3[m, 2K:3K]=lo
// B3[0:K, n]=hi, B3[K:2K, n]=lo, B3[2K:3K, n]=hi
// so A3 @ B3 (over 3K) = Ah*Bh + Ah*Bl + Al*Bh.
// ---------------------------------------------------------------------------
__global__ __launch_bounds__(256) void expand_a3(
    const float* __restrict__ src, __nv_bfloat16* __restrict__ dst, int M, int K)
{
    int idx = blockIdx.x*256 + threadIdx.x;
    if (idx >= M*K) return;
    int m = idx / K, k = idx - m*K;
    float x = src[idx];
    __nv_bfloat16 h = __float2bfloat16(x);
    __nv_bfloat16 l = __float2bfloat16(x - __bfloat162float(h));
    size_t base = (size_t)m*3*K;
    dst[base + k] = h;
    dst[base + K + k] = h;
    dst[base + 2*K + k] = l;
}

__global__ __launch_bounds__(256) void expand_b3(
    const float* __restrict__ src, __nv_bfloat16* __restrict__ dst, int K, int N)
{
    int idx = blockIdx.x*256 + threadIdx.x;
    if (idx >= K*N) return;
    int k = idx / N, n = idx - k*N;
    float x = src[idx];
    __nv_bfloat16 h = __float2bfloat16(x);
    __nv_bfloat16 l = __float2bfloat16(x - __bfloat162float(h));
    dst[(size_t)k*N + n]         = h;
    dst[(size_t)(K+k)*N + n]     = l;
    dst[(size_t)(2*K+k)*N + n]   = h;
}

// ---------------------------------------------------------------------------
// bf16 tensor-core GEMM (R3-exact, proven): C = A3 @ B3 + bias
// Block tile 128x128, 256 threads (8 warps as 2x4), warp tile 64x32,
// mma.sync m16n8k16. Smem padded stride 36 bf16 (18 u32).
// ---------------------------------------------------------------------------
__global__ __launch_bounds__(256) void gemm_bf16(
    const __nv_bfloat16* __restrict__ A, const __nv_bfloat16* __restrict__ B,
    const float* __restrict__ bias, float* __restrict__ C,
    int M, int N, int Kx)
{
    __shared__ uint32_t As[128*18];   // [row][k-u32], 32 bf16 per row + pad
    __shared__ uint32_t Bs[128*18];   // [n][k-u32] (transposed), + pad

    int tid = threadIdx.x;
    int lane = tid & 31;
    int w = tid >> 5;
    int wm = w >> 2;          // 0..1  -> m offset 64*wm
    int wn = w & 3;           // 0..3  -> n offset 32*wn
    int g = lane >> 2;        // group 0..7
    int t = lane & 3;

    int m0 = blockIdx.y * 128;
    int n0 = blockIdx.x * 128;

    float acc[4][4][4];
    #pragma unroll
    for (int i = 0; i < 4; i++)
        #pragma unroll
        for (int j = 0; j < 4; j++)
            #pragma unroll
            for (int r = 0; r < 4; r++) acc[i][j][r] = 0.f;

    __nv_bfloat16* Bsh = (__nv_bfloat16*)Bs;

    for (int k0 = 0; k0 < Kx; k0 += 32) {
        // A tile: 128 rows x 16 u32
        #pragma unroll
        for (int i = 0; i < 8; i++) {
            int u = tid + i*256;
            int r = u >> 4, c = u & 15;
            const uint32_t* ga = (const uint32_t*)(A + (size_t)(m0+r)*Kx + k0);
            As[r*18 + c] = ga[c];
        }
        // B tile: 32 k-rows x 128 n, transposed into Bs[n][k]
        #pragma unroll
        for (int i = 0; i < 8; i++) {
            int u = tid + i*256;
            int k = u >> 6, nc = u & 63;
            const uint32_t* gb = (const uint32_t*)(B + (size_t)(k0+k)*N + n0);
            uint32_t val = gb[nc];
            Bsh[(2*nc)*36 + k]   = ((__nv_bfloat16*)&val)[0];
            Bsh[(2*nc+1)*36 + k] = ((__nv_bfloat16*)&val)[1];
        }
        __syncthreads();

        #pragma unroll
        for (int s = 0; s < 2; s++) {
            uint32_t a[4][4], b[4][2];
            #pragma unroll
            for (int mt = 0; mt < 4; mt++) {
                int ar = (wm*64 + mt*16 + g)*18 + s*8 + t;
                a[mt][0] = As[ar];
                a[mt][1] = As[ar + 8*18];
                a[mt][2] = As[ar + 4];
                a[mt][3] = As[ar + 8*18 + 4];
            }
            #pragma unroll
            for (int nt = 0; nt < 4; nt++) {
                int br = (wn*32 + nt*8 + g)*18 + s*8 + t;
                b[nt][0] = Bs[br];
                b[nt][1] = Bs[br + 4];
            }
            #pragma unroll
            for (int mt = 0; mt < 4; mt++)
                #pragma unroll
                for (int nt = 0; nt < 4; nt++) {
                    asm volatile(
                        "mma.sync.aligned.m16n8k16.row.col.f32.bf16.bf16.f32 "
                        "{%0,%1,%2,%3}, {%4,%5,%6,%7}, {%8,%9}, {%0,%1,%2,%3};"
                        : "+f"(acc[mt][nt][0]), "+f"(acc[mt][nt][1]),
                          "+f"(acc[mt][nt][2]), "+f"(acc[mt][nt][3])
                        : "r"(a[mt][0]), "r"(a[mt][1]), "r"(a[mt][2]), "r"(a[mt][3]),
                          "r"(b[nt][0]), "r"(b[nt][1]));
                }
        }
        __syncthreads();
    }

    // Epilogue: add bias, write fp32
    #pragma unroll
    for (int mt = 0; mt < 4; mt++) {
        int row0 = m0 + wm*64 + mt*16 + g;
        #pragma unroll
        for (int nt = 0; nt < 4; nt++) {
            int col = n0 + wn*32 + nt*8 + 2*t;
            float b0 = bias[col], b1 = bias[col+1];
            C[(size_t)row0*N + col]     = acc[mt][nt][0] + b0;
            C[(size_t)row0*N + col + 1] = acc[mt][nt][1] + b1;
            C[(size_t)(row0+8)*N + col]     = acc[mt][nt][2] + b0;
            C[(size_t)(row0+8)*N + col + 1] = acc[mt][nt][3] + b1;
        }
    }
}

// ---------------------------------------------------------------------------
// Flash attention fp32 SIMT with PARALLEL softmax (4 threads/row).
// One block per (64 q-rows, head, batch), k-tiles of 32, 256 threads.
// ---------------------------------------------------------------------------
#define PST 68
#define PSS 36

__global__ __launch_bounds__(256) void attn_kernel()
{
    __shared__ float Qs[64*PST];
    __shared__ float Ks[32*PST];
    __shared__ float Vs[32*PST];
    __shared__ float Ps[64*PSS];
    __shared__ float mrow[64], lrow[64], arow[64];
    __shared__ float pmax[64][4];
    __shared__ float psum[64][4];

    int tid = threadIdx.x;
    int q0 = blockIdx.x * 64;
    int h  = blockIdx.y;
    int b  = blockIdx.z;
    const float scale = 0.125f;

    int sx = tid & 7;
    int sy = tid >> 3;
    int ox = tid & 15;
    int oy = tid >> 4;
    int rr = tid >> 2;        // softmax row 0..63
    int rp = tid & 3;         // softmax part 0..3 (8 cols each)

    const float* Qg = g_q + (size_t)(b*SQ + q0)*DM + h*HD;
    #pragma unroll
    for (int i = 0; i < 4; i++) {
        int idx4 = tid + i*256;
        int r = idx4 >> 4, c4 = idx4 & 15;
        float4 v = *(const float4*)(Qg + (size_t)r*DM + c4*4);
        v.x *= scale; v.y *= scale; v.z *= scale; v.w *= scale;
        *(float4*)&Qs[r*PST + c4*4] = v;
    }
    if (tid < 64) { mrow[tid] = -INFINITY; lrow[tid] = 0.f; }

    float o[4][4] = {};
    __syncthreads();

    for (int k0 = 0; k0 < SQ; k0 += 32) {
        const float* Kg = g_k + (size_t)(b*SQ + k0)*DM + h*HD;
        const float* Vg = g_v + (size_t)(b*SQ + k0)*DM + h*HD;
        #pragma unroll
        for (int i = 0; i < 2; i++) {
            int idx4 = tid + i*256;
            int r = idx4 >> 4, c4 = idx4 & 15;
            *(float4*)&Ks[r*PST + c4*4] = *(const float4*)(Kg + (size_t)r*DM + c4*4);
            *(float4*)&Vs[r*PST + c4*4] = *(const float4*)(Vg + (size_t)r*DM + c4*4);
        }
        __syncthreads();

        // S = Q @ K^T : 2 q-rows x 4 k-cols per thread
        float s[2][4] = {};
        #pragma unroll 16
        for (int d = 0; d < 64; d++) {
            float qv[2], kv[4];
            qv[0] = Qs[sy*PST + d];
            qv[1] = Qs[(sy+32)*PST + d];
            #pragma unroll
            for (int j = 0; j < 4; j++) kv[j] = Ks[(sx*4+j)*PST + d];
            #pragma unroll
            for (int i = 0; i < 2; i++)
                #pragma unroll
                for (int j = 0; j < 4; j++)
                    s[i][j] = fmaf(qv[i], kv[j], s[i][j]);
        }
        #pragma unroll
        for (int i = 0; i < 2; i++) {
            int q = sy + 32*i;
            *(float4*)&Ps[q*PSS + sx*4] = make_float4(s[i][0], s[i][1], s[i][2], s[i][3]);
        }
        __syncthreads();

        // Softmax phase A: per-thread max over its 8 cols
        {
            float mx = -INFINITY;
            #pragma unroll
            for (int j = 0; j < 8; j++)
                mx = fmaxf(mx, Ps[rr*PSS + rp*8 + j]);
            pmax[rr][rp] = mx;
        }
        __syncthreads();

        // Softmax phase B: full row max (redundant per 4 threads), exp + partial sum
        {
            float mx = fmaxf(fmaxf(pmax[rr][0], pmax[rr][1]),
                             fmaxf(pmax[rr][2], pmax[rr][3]));
            mx = fmaxf(mx, mrow[rr]);
            float sum = 0.f;
            #pragma unroll
            for (int j = 0; j < 8; j++) {
                float p = __expf(Ps[rr*PSS + rp*8 + j] - mx);
                Ps[rr*PSS + rp*8 + j] = p;
                sum += p;
            }
            psum[rr][rp] = sum;
            if (rp == 0) {
                float mo = mrow[rr];
                float al = __expf(mo - mx);
                arow[rr] = al;
                mrow[rr] = mx;
            }
        }
        __syncthreads();

        if (tid < 64) {
            float tot = psum[tid][0] + psum[tid][1] + psum[tid][2] + psum[tid][3];
            lrow[tid] = lrow[tid]*arow[tid] + tot;
        }
        __syncthreads();

        // O += P @ V : 4 q-rows x 4 hd-cols per thread, rescale first
        float al[4];
        #pragma unroll
        for (int i = 0; i < 4; i++) al[i] = arow[oy + 16*i];
        #pragma unroll
        for (int i = 0; i < 4; i++)
            #pragma unroll
            for (int j = 0; j < 4; j++)
                o[i][j] *= al[i];

        #pragma unroll 8
        for (int kk = 0; kk < 32; kk++) {
            float pv[4], vv[4];
            #pragma unroll
            for (int i = 0; i < 4; i++) pv[i] = Ps[(oy + 16*i)*PSS + kk];
            #pragma unroll
            for (int j = 0; j < 4; j++) vv[j] = Vs[kk*PST + ox*4 + j];
            #pragma unroll
            for (int i = 0; i < 4; i++)
                #pragma unroll
                for (int j = 0; j < 4; j++)
                    o[i][j] = fmaf(pv[i], vv[j], o[i][j]);
        }
        __syncthreads();
    }

    float* Og = g_o + (size_t)(b*SQ + q0)*DM + h*HD;
    #pragma unroll
    for (int i = 0; i < 4; i++) {
        int q = oy + 16*i;
        float inv = 1.f / lrow[q];
        #pragma unroll
        for (int j = 0; j < 4; j++)
            Og[(size_t)q*DM + ox*4 + j] = o[i][j] * inv;
    }
}

extern "C" void kernel_launch(void* const* d_in, const int* in_sizes, int n_in,
                              void* d_out, int out_size)
{
    const float* x  = (const float*)d_in[0];
    const float* wq = (const float*)d_in[1];
    const float* bq = (const float*)d_in[2];
    const float* wk = (const float*)d_in[3];
    const float* bk = (const float*)d_in[4];
    const float* wv = (const float*)d_in[5];
    const float* bv = (const float*)d_in[6];
    const float* wo = (const float*)d_in[7];
    const float* bo = (const float*)d_in[8];
    float* out = (float*)d_out;

    float *q, *k, *v, *o;
    __nv_bfloat16 *x3, *o3, *wq3, *wk3, *wv3, *wo3;
    cudaGetSymbolAddress((void**)&q, g_q);
    cudaGetSymbolAddress((void**)&k, g_k);
    cudaGetSymbolAddress((void**)&v, g_v);
    cudaGetSymbolAddress((void**)&o, g_o);
    cudaGetSymbolAddress((void**)&x3, g_x3);
    cudaGetSymbolAddress((void**)&o3, g_o3);
    cudaGetSymbolAddress((void**)&wq3, g_wq3);
    cudaGetSymbolAddress((void**)&wk3, g_wk3);
    cudaGetSymbolAddress((void**)&wv3, g_wv3);
    cudaGetSymbolAddress((void**)&wo3, g_wo3);

    int eb = (MR*DM + 255)/256;     // activations
    int wb = (DM*DM + 255)/256;     // weights

    dim3 gg(DM/128, MR/128);        // (8, 32)

    // Launch order arranged so launches #5-7 are gemm_bf16 (ncu -s 5 lands on a GEMM)
    expand_a3<<<eb, 256>>>(x, x3, MR, DM);          // 1
    expand_b3<<<wb, 256>>>(wq, wq3, DM, DM);        // 2
    expand_b3<<<wb, 256>>>(wk, wk3, DM, DM);        // 3
    expand_b3<<<wb, 256>>>(wv, wv3, DM, DM);        // 4
    gemm_bf16<<<gg, 256>>>(x3, wq3, bq, q, MR, DM, K3);   // 5
    gemm_bf16<<<gg, 256>>>(x3, wk3, bk, k, MR, DM, K3);   // 6
    gemm_bf16<<<gg, 256>>>(x3, wv3, bv, v, MR, DM, K3);   // 7

    attn_kernel<<<dim3(SQ/64, HH, BZ), 256>>>();          // 8

    expand_a3<<<eb, 256>>>(o, o3, MR, DM);                // 9
    expand_b3<<<wb, 256>>>(wo, wo3, DM, DM);              // 10
    gemm_bf16<<<gg, 256>>>(o3, wo3, bo, out, MR, DM, K3); // 11
}

// round 11
// speedup vs baseline: 3.2219x; 1.9304x over previous
#include <cuda_runtime.h>
#include <cuda_bf16.h>
#include <cstdint>
#include <math.h>

#define BZ   2
#define SQ   2048
#define DM   1024
#define HH   16
#define HD   64
#define MR   (BZ*SQ)      // 4096 rows
#define K3   (3*DM)       // 3072 expanded-K

// ---- device-global scratch (no allocations allowed) ----
__device__ float g_q[(size_t)MR*DM];
__device__ float g_k[(size_t)MR*DM];
__device__ float g_v[(size_t)MR*DM];
__device__ float g_o[(size_t)MR*DM];
__device__ __align__(16) __nv_bfloat16 g_x3[(size_t)MR*K3];
__device__ __align__(16) __nv_bfloat16 g_o3[(size_t)MR*K3];
__device__ __align__(16) __nv_bfloat16 g_wq3[(size_t)DM*K3];   // transposed [N][K3]
__device__ __align__(16) __nv_bfloat16 g_wk3[(size_t)DM*K3];
__device__ __align__(16) __nv_bfloat16 g_wv3[(size_t)DM*K3];
__device__ __align__(16) __nv_bfloat16 g_wo3[(size_t)DM*K3];

// ---------------------------------------------------------------------------
// Split-expansion: hi = bf16(x), lo = bf16(x - hi)
// A3[m][0:K]=h, [K:2K]=h, [2K:3K]=l    (row-major [M][3K])
// B3t[n][0:K]=h, [K:2K]=l, [2K:3K]=h   (TRANSPOSED [N][3K], K-major)
// => dot over 3K = Ah*Bh + Ah*Bl + Al*Bh
// ---------------------------------------------------------------------------
__global__ __launch_bounds__(256) void expand_a3(
    const float* __restrict__ src, __nv_bfloat16* __restrict__ dst, int M, int K)
{
    int idx = blockIdx.x*256 + threadIdx.x;
    if (idx >= M*K) return;
    int m = idx / K, k = idx - m*K;
    float x = src[idx];
    __nv_bfloat16 h = __float2bfloat16(x);
    __nv_bfloat16 l = __float2bfloat16(x - __bfloat162float(h));
    size_t base = (size_t)m*3*K;
    dst[base + k] = h;
    dst[base + K + k] = h;
    dst[base + 2*K + k] = l;
}

// transpose-expand: src [K][N] -> dst [N][3K] with blocks [h | l | h]
__global__ __launch_bounds__(256) void expand_b3t(
    const float* __restrict__ src, __nv_bfloat16* __restrict__ dst, int K, int N)
{
    __shared__ float t[32][33];
    int tx = threadIdx.x & 31, ty = threadIdx.x >> 5;   // 32 x 8
    int nb = blockIdx.x * 32, kb = blockIdx.y * 32;
    #pragma unroll
    for (int i = 0; i < 4; i++)
        t[ty + 8*i][tx] = src[(size_t)(kb + ty + 8*i)*N + nb + tx];
    __syncthreads();
    #pragma unroll
    for (int i = 0; i < 4; i++) {
        int n = nb + ty + 8*i;
        int k = kb + tx;
        float x = t[tx][ty + 8*i];   // src[k][n]
        __nv_bfloat16 h = __float2bfloat16(x);
        __nv_bfloat16 l = __float2bfloat16(x - __bfloat162float(h));
        size_t base = (size_t)n*3*K;
        dst[base + k]       = h;
        dst[base + K + k]   = l;
        dst[base + 2*K + k] = h;
    }
}

// ---------------------------------------------------------------------------
// bf16 HMMA GEMM v4: C[M,N] = A3[M,Kx] @ B3t[N,Kx]^T + bias
// R3 structure (single buffer, 2 CTAs/SM) but: B pre-transposed (no in-kernel
// transpose) and uint4 tile fills. Row stride 20 u32 (16B-aligned uint4
// slots; fragment banks 20g+t all distinct across warp).
// ---------------------------------------------------------------------------
#define AST 20

__global__ __launch_bounds__(256) void gemm_bf16(
    const __nv_bfloat16* __restrict__ A, const __nv_bfloat16* __restrict__ Bt,
    const float* __restrict__ bias, float* __restrict__ C,
    int M, int N, int Kx)
{
    __shared__ __align__(16) uint32_t As[128*AST];   // 10 KB
    __shared__ __align__(16) uint32_t Bs[128*AST];   // 10 KB

    int tid = threadIdx.x;
    int lane = tid & 31;
    int w = tid >> 5;
    int wm = w >> 2;          // 0..1
    int wn = w & 3;           // 0..3
    int g = lane >> 2;        // 0..7
    int t = lane & 3;         // 0..3

    int m0 = blockIdx.y * 128;
    int n0 = blockIdx.x * 128;

    // tile fill mapping: 512 uint4 per operand; 2 per thread
    const int r0 = tid >> 2,  c0 = tid & 3;
    const int r1 = r0 + 64,   c1 = c0;

    const __nv_bfloat16* pA0 = A  + (size_t)(m0 + r0)*Kx + c0*8;
    const __nv_bfloat16* pA1 = A  + (size_t)(m0 + r1)*Kx + c1*8;
    const __nv_bfloat16* pB0 = Bt + (size_t)(n0 + r0)*Kx + c0*8;
    const __nv_bfloat16* pB1 = Bt + (size_t)(n0 + r1)*Kx + c1*8;

    float acc[4][4][4];
    #pragma unroll
    for (int i = 0; i < 4; i++)
        #pragma unroll
        for (int j = 0; j < 4; j++)
            #pragma unroll
            for (int r = 0; r < 4; r++) acc[i][j][r] = 0.f;

    for (int k0 = 0; k0 < Kx; k0 += 32) {
        *(uint4*)&As[r0*AST + c0*4] = *(const uint4*)(pA0 + k0);
        *(uint4*)&As[r1*AST + c1*4] = *(const uint4*)(pA1 + k0);
        *(uint4*)&Bs[r0*AST + c0*4] = *(const uint4*)(pB0 + k0);
        *(uint4*)&Bs[r1*AST + c1*4] = *(const uint4*)(pB1 + k0);
        __syncthreads();

        #pragma unroll
        for (int s = 0; s < 2; s++) {
            uint32_t a[4][4], b[4][2];
            #pragma unroll
            for (int mt = 0; mt < 4; mt++) {
                int ar = (wm*64 + mt*16 + g)*AST + s*8 + t;
                a[mt][0] = As[ar];
                a[mt][1] = As[ar + 8*AST];
                a[mt][2] = As[ar + 4];
                a[mt][3] = As[ar + 8*AST + 4];
            }
            #pragma unroll
            for (int nt = 0; nt < 4; nt++) {
                int br = (wn*32 + nt*8 + g)*AST + s*8 + t;
                b[nt][0] = Bs[br];
                b[nt][1] = Bs[br + 4];
            }
            #pragma unroll
            for (int mt = 0; mt < 4; mt++)
                #pragma unroll
                for (int nt = 0; nt < 4; nt++) {
                    asm volatile(
                        "mma.sync.aligned.m16n8k16.row.col.f32.bf16.bf16.f32 "
                        "{%0,%1,%2,%3}, {%4,%5,%6,%7}, {%8,%9}, {%0,%1,%2,%3};"
                        : "+f"(acc[mt][nt][0]), "+f"(acc[mt][nt][1]),
                          "+f"(acc[mt][nt][2]), "+f"(acc[mt][nt][3])
                        : "r"(a[mt][0]), "r"(a[mt][1]), "r"(a[mt][2]), "r"(a[mt][3]),
                          "r"(b[nt][0]), "r"(b[nt][1]));
                }
        }
        __syncthreads();
    }

    #pragma unroll
    for (int mt = 0; mt < 4; mt++) {
        int row0 = m0 + wm*64 + mt*16 + g;
        #pragma unroll
        for (int nt = 0; nt < 4; nt++) {
            int col = n0 + wn*32 + nt*8 + 2*t;
            float b0 = bias[col], b1 = bias[col+1];
            C[(size_t)row0*N + col]         = acc[mt][nt][0] + b0;
            C[(size_t)row0*N + col + 1]     = acc[mt][nt][1] + b1;
            C[(size_t)(row0+8)*N + col]     = acc[mt][nt][2] + b0;
            C[(size_t)(row0+8)*N + col + 1] = acc[mt][nt][3] + b1;
        }
    }
}

// ---------------------------------------------------------------------------
// Flash attention fp32 SIMT, float4-vectorized inner loops.
// One block per (64 q-rows, head, batch), k-tiles of 32, 256 threads.
// S cols per thread: sx + 8j (8 consecutive K-rows per ldmatrix phase ->
// conflict-free float4 K loads).
// ---------------------------------------------------------------------------
#define PST 68
#define PSS 36

__global__ __launch_bounds__(256) void attn_kernel()
{
    __shared__ float Qs[64*PST];
    __shared__ float Ks[32*PST];
    __shared__ float Vs[32*PST];
    __shared__ float Ps[64*PSS];
    __shared__ float mrow[64], lrow[64], arow[64];
    __shared__ float pmax[64][4];
    __shared__ float psum[64][4];

    int tid = threadIdx.x;
    int q0 = blockIdx.x * 64;
    int h  = blockIdx.y;
    int b  = blockIdx.z;
    const float scale = 0.125f;

    int sx = tid & 7;         // S col base (cols sx+8j)
    int sy = tid >> 3;        // S rows sy, sy+32
    int ox = tid & 15;        // PV col group ox*4..+3
    int oy = tid >> 4;        // PV rows oy+16i
    int rr = tid >> 2;        // softmax row
    int rp = tid & 3;         // softmax part (8 cols)

    const float* Qg = g_q + (size_t)(b*SQ + q0)*DM + h*HD;
    #pragma unroll
    for (int i = 0; i < 4; i++) {
        int idx4 = tid + i*256;
        int r = idx4 >> 4, c4 = idx4 & 15;
        float4 v = *(const float4*)(Qg + (size_t)r*DM + c4*4);
        v.x *= scale; v.y *= scale; v.z *= scale; v.w *= scale;
        *(float4*)&Qs[r*PST + c4*4] = v;
    }
    if (tid < 64) { mrow[tid] = -INFINITY; lrow[tid] = 0.f; }

    float o[4][4] = {};
    __syncthreads();

    for (int k0 = 0; k0 < SQ; k0 += 32) {
        const float* Kg = g_k + (size_t)(b*SQ + k0)*DM + h*HD;
        const float* Vg = g_v + (size_t)(b*SQ + k0)*DM + h*HD;
        #pragma unroll
        for (int i = 0; i < 2; i++) {
            int idx4 = tid + i*256;
            int r = idx4 >> 4, c4 = idx4 & 15;
            *(float4*)&Ks[r*PST + c4*4] = *(const float4*)(Kg + (size_t)r*DM + c4*4);
            *(float4*)&Vs[r*PST + c4*4] = *(const float4*)(Vg + (size_t)r*DM + c4*4);
        }
        __syncthreads();

        // S = Q @ K^T : 2 q-rows x 4 k-cols, float4 over d
        float s[2][4] = {};
        #pragma unroll
        for (int d0 = 0; d0 < 64; d0 += 4) {
            float4 q0v = *(const float4*)&Qs[sy*PST + d0];
            float4 q1v = *(const float4*)&Qs[(sy+32)*PST + d0];
            #pragma unroll
            for (int j = 0; j < 4; j++) {
                float4 kv = *(const float4*)&Ks[(sx + 8*j)*PST + d0];
                s[0][j] += q0v.x*kv.x + q0v.y*kv.y + q0v.z*kv.z + q0v.w*kv.w;
                s[1][j] += q1v.x*kv.x + q1v.y*kv.y + q1v.z*kv.z + q1v.w*kv.w;
            }
        }
        #pragma unroll
        for (int i = 0; i < 2; i++) {
            int q = sy + 32*i;
            #pragma unroll
            for (int j = 0; j < 4; j++)
                Ps[q*PSS + sx + 8*j] = s[i][j];
        }
        __syncthreads();

        // Softmax A: partial max
        {
            float mx = -INFINITY;
            #pragma unroll
            for (int j = 0; j < 8; j++)
                mx = fmaxf(mx, Ps[rr*PSS + rp*8 + j]);
            pmax[rr][rp] = mx;
        }
        __syncthreads();

        // Softmax B: row max, exp, partial sums
        {
            float mx = fmaxf(fmaxf(pmax[rr][0], pmax[rr][1]),
                             fmaxf(pmax[rr][2], pmax[rr][3]));
            mx = fmaxf(mx, mrow[rr]);
            float sum = 0.f;
            #pragma unroll
            for (int j = 0; j < 8; j++) {
                float p = __expf(Ps[rr*PSS + rp*8 + j] - mx);
                Ps[rr*PSS + rp*8 + j] = p;
                sum += p;
            }
            psum[rr][rp] = sum;
            if (rp == 0) {
                float al = __expf(mrow[rr] - mx);
                arow[rr] = al;
                mrow[rr] = mx;
            }
        }
        __syncthreads();

        if (tid < 64) {
            float tot = psum[tid][0] + psum[tid][1] + psum[tid][2] + psum[tid][3];
            lrow[tid] = lrow[tid]*arow[tid] + tot;
        }
        __syncthreads();

        // O += P @ V : 4 q-rows x 4 hd-cols, float4 over kk
        float al[4];
        #pragma unroll
        for (int i = 0; i < 4; i++) al[i] = arow[oy + 16*i];
        #pragma unroll
        for (int i = 0; i < 4; i++)
            #pragma unroll
            for (int j = 0; j < 4; j++)
                o[i][j] *= al[i];

        #pragma unroll
        for (int k4 = 0; k4 < 32; k4 += 4) {
            float4 pv[4];
            #pragma unroll
            for (int i = 0; i < 4; i++)
                pv[i] = *(const float4*)&Ps[(oy + 16*i)*PSS + k4];
            float vv[4][4];
            #pragma unroll
            for (int kk = 0; kk < 4; kk++)
                *(float4*)vv[kk] = *(const float4*)&Vs[(k4+kk)*PST + ox*4];
            #pragma unroll
            for (int i = 0; i < 4; i++)
                #pragma unroll
                for (int j = 0; j < 4; j++)
                    o[i][j] += pv[i].x*vv[0][j] + pv[i].y*vv[1][j]
                             + pv[i].z*vv[2][j] + pv[i].w*vv[3][j];
        }
        __syncthreads();
    }

    float* Og = g_o + (size_t)(b*SQ + q0)*DM + h*HD;
    #pragma unroll
    for (int i = 0; i < 4; i++) {
        int q = oy + 16*i;
        float inv = 1.f / lrow[q];
        #pragma unroll
        for (int j = 0; j < 4; j++)
            Og[(size_t)q*DM + ox*4 + j] = o[i][j] * inv;
    }
}

extern "C" void kernel_launch(void* const* d_in, const int* in_sizes, int n_in,
                              void* d_out, int out_size)
{
    const float* x  = (const float*)d_in[0];
    const float* wq = (const float*)d_in[1];
    const float* bq = (const float*)d_in[2];
    const float* wk = (const float*)d_in[3];
    const float* bk = (const float*)d_in[4];
    const float* wv = (const float*)d_in[5];
    const float* bv = (const float*)d_in[6];
    const float* wo = (const float*)d_in[7];
    const float* bo = (const float*)d_in[8];
    float* out = (float*)d_out;

    float *q, *k, *v, *o;
    __nv_bfloat16 *x3, *o3, *wq3, *wk3, *wv3, *wo3;
    cudaGetSymbolAddress((void**)&q, g_q);
    cudaGetSymbolAddress((void**)&k, g_k);
    cudaGetSymbolAddress((void**)&v, g_v);
    cudaGetSymbolAddress((void**)&o, g_o);
    cudaGetSymbolAddress((void**)&x3, g_x3);
    cudaGetSymbolAddress((void**)&o3, g_o3);
    cudaGetSymbolAddress((void**)&wq3, g_wq3);
    cudaGetSymbolAddress((void**)&wk3, g_wk3);
    cudaGetSymbolAddress((void**)&wv3, g_wv3);
    cudaGetSymbolAddress((void**)&wo3, g_wo3);

    int eb = (MR*DM + 255)/256;
    dim3 tb(DM/32, DM/32);          // 32x32 transpose tiles
    dim3 gg(DM/128, MR/128);        // (8, 32)

    // Launches #5-7 are gemm_bf16 (ncu -s 5 lands on a GEMM)
    expand_a3<<<eb, 256>>>(x, x3, MR, DM);                 // 1
    expand_b3t<<<tb, 256>>>(wq, wq3, DM, DM);              // 2
    expand_b3t<<<tb, 256>>>(wk, wk3, DM, DM);              // 3
    expand_b3t<<<tb, 256>>>(wv, wv3, DM, DM);              // 4
    gemm_bf16<<<gg, 256>>>(x3, wq3, bq, q, MR, DM, K3);    // 5
    gemm_bf16<<<gg, 256>>>(x3, wk3, bk, k, MR, DM, K3);    // 6
    gemm_bf16<<<gg, 256>>>(x3, wv3, bv, v, MR, DM, K3);    // 7

    attn_kernel<<<dim3(SQ/64, HH, BZ), 256>>>();           // 8

    expand_a3<<<eb, 256>>>(o, o3, MR, DM);                 // 9
    expand_b3t<<<tb, 256>>>(wo, wo3, DM, DM);              // 10
    gemm_bf16<<<gg, 256>>>(o3, wo3, bo, out, MR, DM, K3);  // 11
}

// round 12
// speedup vs baseline: 4.8933x; 1.5188x over previous
#include <cuda_runtime.h>
#include <cuda_bf16.h>
#include <cstdint>
#include <math.h>

#define BZ   2
#define SQ   2048
#define DM   1024
#define HH   16
#define HD   64
#define MR   (BZ*SQ)      // 4096 rows
#define K3   (3*DM)       // 3072 expanded-K

// ---- device-global scratch (no allocations allowed) ----
__device__ float g_q[(size_t)MR*DM];
__device__ float g_k[(size_t)MR*DM];
__device__ float g_v[(size_t)MR*DM];
__device__ float g_o[(size_t)MR*DM];
__device__ __align__(16) __nv_bfloat16 g_x3[(size_t)MR*K3];
__device__ __align__(16) __nv_bfloat16 g_o3[(size_t)MR*K3];
__device__ __align__(16) __nv_bfloat16 g_wq3[(size_t)DM*K3];   // [N][K3]
__device__ __align__(16) __nv_bfloat16 g_wk3[(size_t)DM*K3];
__device__ __align__(16) __nv_bfloat16 g_wv3[(size_t)DM*K3];
__device__ __align__(16) __nv_bfloat16 g_wo3[(size_t)DM*K3];
// attention split operands (per head):
__device__ __align__(16) __nv_bfloat16 g_q3[(size_t)BZ*HH*SQ*192];     // [bh][s][h|h|l]
__device__ __align__(16) __nv_bfloat16 g_k3[(size_t)BZ*HH*SQ*192];     // [bh][s][h|l|h]
__device__ __align__(16) __nv_bfloat16 g_v3t[(size_t)BZ*HH*HD*3*SQ];   // [bh][hd][Vh|Vl|Vh over s]

// ---------------------------------------------------------------------------
// GEMM-side expansion (unchanged, proven)
// ---------------------------------------------------------------------------
__global__ __launch_bounds__(256) void expand_a3(
    const float* __restrict__ src, __nv_bfloat16* __restrict__ dst, int M, int K)
{
    int idx = blockIdx.x*256 + threadIdx.x;
    if (idx >= M*K) return;
    int m = idx / K, k = idx - m*K;
    float x = src[idx];
    __nv_bfloat16 h = __float2bfloat16(x);
    __nv_bfloat16 l = __float2bfloat16(x - __bfloat162float(h));
    size_t base = (size_t)m*3*K;
    dst[base + k] = h;
    dst[base + K + k] = h;
    dst[base + 2*K + k] = l;
}

__global__ __launch_bounds__(256) void expand_b3t(
    const float* __restrict__ src, __nv_bfloat16* __restrict__ dst, int K, int N)
{
    __shared__ float t[32][33];
    int tx = threadIdx.x & 31, ty = threadIdx.x >> 5;
    int nb = blockIdx.x * 32, kb = blockIdx.y * 32;
    #pragma unroll
    for (int i = 0; i < 4; i++)
        t[ty + 8*i][tx] = src[(size_t)(kb + ty + 8*i)*N + nb + tx];
    __syncthreads();
    #pragma unroll
    for (int i = 0; i < 4; i++) {
        int n = nb + ty + 8*i;
        int k = kb + tx;
        float x = t[tx][ty + 8*i];
        __nv_bfloat16 h = __float2bfloat16(x);
        __nv_bfloat16 l = __float2bfloat16(x - __bfloat162float(h));
        size_t base = (size_t)n*3*K;
        dst[base + k]       = h;
        dst[base + K + k]   = l;
        dst[base + 2*K + k] = h;
    }
}

// ---------------------------------------------------------------------------
// Attention-side expansions
// Q: [h|h|l] over d (pre-scaled 0.125); K: [h|l|h] over d
// ---------------------------------------------------------------------------
__global__ __launch_bounds__(256) void expand_q3k3(
    const float* __restrict__ qsrc, const float* __restrict__ ksrc)
{
    int idx = blockIdx.x*256 + threadIdx.x;   // over MR*DM
    int d  = idx & 1023;
    int bs = idx >> 10;
    int h = d >> 6, hd = d & 63;
    int b = bs >> 11, s = bs & 2047;
    size_t base = ((size_t)(b*HH + h)*SQ + s)*192;

    float xq = qsrc[idx] * 0.125f;
    __nv_bfloat16 qh = __float2bfloat16(xq);
    __nv_bfloat16 ql = __float2bfloat16(xq - __bfloat162float(qh));
    g_q3[base + hd]       = qh;
    g_q3[base + 64 + hd]  = qh;
    g_q3[base + 128 + hd] = ql;

    float xk = ksrc[idx];
    __nv_bfloat16 kh = __float2bfloat16(xk);
    __nv_bfloat16 kl = __float2bfloat16(xk - __bfloat162float(kh));
    g_k3[base + hd]       = kh;
    g_k3[base + 64 + hd]  = kl;
    g_k3[base + 128 + hd] = kh;
}

// V transpose-expand: per (b,h): dst [hd][3*SQ] = [Vh | Vl | Vh] over s
__global__ __launch_bounds__(256) void expand_v3t(const float* __restrict__ src)
{
    __shared__ float t[32][33];
    int tx = threadIdx.x & 31, ty = threadIdx.x >> 5;
    int s0 = blockIdx.x * 32;
    int hd0 = blockIdx.y * 32;
    int bh = blockIdx.z;               // b*16 + h
    int b = bh >> 4, h = bh & 15;
    #pragma unroll
    for (int i = 0; i < 4; i++)
        t[ty + 8*i][tx] = src[(size_t)(b*SQ + s0 + ty + 8*i)*DM + h*64 + hd0 + tx];
    __syncthreads();
    #pragma unroll
    for (int i = 0; i < 4; i++) {
        int hd = hd0 + ty + 8*i;
        float x = t[tx][ty + 8*i];
        __nv_bfloat16 hh = __float2bfloat16(x);
        __nv_bfloat16 ll = __float2bfloat16(x - __bfloat162float(hh));
        size_t base = ((size_t)bh*HD + hd)*3*SQ;
        g_v3t[base + s0 + tx]        = hh;
        g_v3t[base + SQ + s0 + tx]   = ll;
        g_v3t[base + 2*SQ + s0 + tx] = hh;
    }
}

// ---------------------------------------------------------------------------
// bf16 HMMA GEMM v4 (unchanged from R11, proven)
// ---------------------------------------------------------------------------
#define AST 20

__global__ __launch_bounds__(256) void gemm_bf16(
    const __nv_bfloat16* __restrict__ A, const __nv_bfloat16* __restrict__ Bt,
    const float* __restrict__ bias, float* __restrict__ C,
    int M, int N, int Kx)
{
    __shared__ __align__(16) uint32_t As[128*AST];
    __shared__ __align__(16) uint32_t Bs[128*AST];

    int tid = threadIdx.x;
    int lane = tid & 31;
    int w = tid >> 5;
    int wm = w >> 2;
    int wn = w & 3;
    int g = lane >> 2;
    int t = lane & 3;

    int m0 = blockIdx.y * 128;
    int n0 = blockIdx.x * 128;

    const int r0 = tid >> 2,  c0 = tid & 3;
    const int r1 = r0 + 64,   c1 = c0;

    const __nv_bfloat16* pA0 = A  + (size_t)(m0 + r0)*Kx + c0*8;
    const __nv_bfloat16* pA1 = A  + (size_t)(m0 + r1)*Kx + c1*8;
    const __nv_bfloat16* pB0 = Bt + (size_t)(n0 + r0)*Kx + c0*8;
    const __nv_bfloat16* pB1 = Bt + (size_t)(n0 + r1)*Kx + c1*8;

    float acc[4][4][4];
    #pragma unroll
    for (int i = 0; i < 4; i++)
        #pragma unroll
        for (int j = 0; j < 4; j++)
            #pragma unroll
            for (int r = 0; r < 4; r++) acc[i][j][r] = 0.f;

    for (int k0 = 0; k0 < Kx; k0 += 32) {
        *(uint4*)&As[r0*AST + c0*4] = *(const uint4*)(pA0 + k0);
        *(uint4*)&As[r1*AST + c1*4] = *(const uint4*)(pA1 + k0);
        *(uint4*)&Bs[r0*AST + c0*4] = *(const uint4*)(pB0 + k0);
        *(uint4*)&Bs[r1*AST + c1*4] = *(const uint4*)(pB1 + k0);
        __syncthreads();

        #pragma unroll
        for (int s = 0; s < 2; s++) {
            uint32_t a[4][4], b[4][2];
            #pragma unroll
            for (int mt = 0; mt < 4; mt++) {
                int ar = (wm*64 + mt*16 + g)*AST + s*8 + t;
                a[mt][0] = As[ar];
                a[mt][1] = As[ar + 8*AST];
                a[mt][2] = As[ar + 4];
                a[mt][3] = As[ar + 8*AST + 4];
            }
            #pragma unroll
            for (int nt = 0; nt < 4; nt++) {
                int br = (wn*32 + nt*8 + g)*AST + s*8 + t;
                b[nt][0] = Bs[br];
                b[nt][1] = Bs[br + 4];
            }
            #pragma unroll
            for (int mt = 0; mt < 4; mt++)
                #pragma unroll
                for (int nt = 0; nt < 4; nt++) {
                    asm volatile(
                        "mma.sync.aligned.m16n8k16.row.col.f32.bf16.bf16.f32 "
                        "{%0,%1,%2,%3}, {%4,%5,%6,%7}, {%8,%9}, {%0,%1,%2,%3};"
                        : "+f"(acc[mt][nt][0]), "+f"(acc[mt][nt][1]),
                          "+f"(acc[mt][nt][2]), "+f"(acc[mt][nt][3])
                        : "r"(a[mt][0]), "r"(a[mt][1]), "r"(a[mt][2]), "r"(a[mt][3]),
                          "r"(b[nt][0]), "r"(b[nt][1]));
                }
        }
        __syncthreads();
    }

    #pragma unroll
    for (int mt = 0; mt < 4; mt++) {
        int row0 = m0 + wm*64 + mt*16 + g;
        #pragma unroll
        for (int nt = 0; nt < 4; nt++) {
            int col = n0 + wn*32 + nt*8 + 2*t;
            float b0 = bias[col], b1 = bias[col+1];
            C[(size_t)row0*N + col]         = acc[mt][nt][0] + b0;
            C[(size_t)row0*N + col + 1]     = acc[mt][nt][1] + b1;
            C[(size_t)(row0+8)*N + col]     = acc[mt][nt][2] + b0;
            C[(size_t)(row0+8)*N + col + 1] = acc[mt][nt][3] + b1;
        }
    }
}

// ---------------------------------------------------------------------------
// HMMA flash attention with 3-term split (fp32-class accuracy).
// Block = (64 q-rows, head, batch); chunk = 32 k-rows; 256 threads.
// S phase: warps 4x2 (wm rows 16*wm, wn cols 16*wn), K'=192, 12 ksteps.
// PV phase: warps 2x4 (wm2 rows 32*wm2, wn2 hd-cols 16*wn2), K'=96, 6 ksteps.
// Smem strides: QST=100 u32 (banks 4g+t), VST=52 u32 (banks 20g+t) -- both
// conflict-free for the proven fragment pattern.
// ---------------------------------------------------------------------------
#define QST 100
#define VST 52

__global__ __launch_bounds__(256) void attn_mma()
{
    __shared__ __align__(16) uint32_t U[6656];     // Q3s(6400) / V3s(3328)+P3s(3328)
    __shared__ __align__(16) uint32_t K3s[32*QST]; // 12.8 KB
    __shared__ float mrow[64], lrow[64], arow[64];
    __shared__ float pmax[64][2], psum[64][2];

    int tid = threadIdx.x, lane = tid & 31, w = tid >> 5;
    int g = lane >> 2, t = lane & 3;
    int q0 = blockIdx.x * 64;
    int bh = blockIdx.z * HH + blockIdx.y;      // b*HH + h

    int wm = w >> 1, wn = w & 1;        // S phase
    int wm2 = w >> 2, wn2 = w & 3;      // PV phase

    // --- load Q3 tile (64 x 192 bf16) and build persistent A-fragments ---
    const __nv_bfloat16* Qg = g_q3 + ((size_t)bh*SQ + q0)*192;
    #pragma unroll
    for (int i = 0; i < 6; i++) {
        int idx = tid + i*256;
        int r = idx / 24, c = idx % 24;
        *(uint4*)&U[r*QST + c*4] = *(const uint4*)(Qg + (size_t)r*192 + c*8);
    }
    if (tid < 64) { mrow[tid] = -INFINITY; lrow[tid] = 0.f; }
    __syncthreads();

    uint32_t qa[12][4];
    #pragma unroll
    for (int ks = 0; ks < 12; ks++) {
        int ar = (wm*16 + g)*QST + ks*8 + t;
        qa[ks][0] = U[ar];
        qa[ks][1] = U[ar + 8*QST];
        qa[ks][2] = U[ar + 4];
        qa[ks][3] = U[ar + 8*QST + 4];
    }
    __syncthreads();    // Q3s region now reusable

    uint32_t* V3s = U;          // [64 hd][VST]
    uint32_t* P3s = U + 3328;   // [64 q][VST]
    __nv_bfloat16* P3h = (__nv_bfloat16*)P3s;

    float o[2][2][4] = {};

    const __nv_bfloat16* Kg = g_k3 + (size_t)bh*SQ*192;
    const __nv_bfloat16* Vg = g_v3t + (size_t)bh*HD*3*SQ;

    for (int k0 = 0; k0 < SQ; k0 += 32) {
        // K3 tile: 32 rows x 24 uint4
        #pragma unroll
        for (int i = 0; i < 3; i++) {
            int idx = tid + i*256;
            int r = idx / 24, c = idx % 24;
            *(uint4*)&K3s[r*QST + c*4] = *(const uint4*)(Kg + (size_t)(k0+r)*192 + c*8);
        }
        // V3 tile: 64 hd-rows x (3 blk x 4 uint4)
        #pragma unroll
        for (int i = 0; i < 3; i++) {
            int idx = tid + i*256;
            int r = idx / 12, sub = idx % 12;
            int blk = sub >> 2, c = sub & 3;
            *(uint4*)&V3s[r*VST + blk*16 + c*4] =
                *(const uint4*)(Vg + (size_t)r*3*SQ + blk*SQ + k0 + c*8);
        }
        __syncthreads();

        // --- S = Q3 @ K3^T (fp32 accum in fragments) ---
        float sc[2][4];
        #pragma unroll
        for (int nt = 0; nt < 2; nt++)
            #pragma unroll
            for (int r = 0; r < 4; r++) sc[nt][r] = 0.f;
        #pragma unroll
        for (int ks = 0; ks < 12; ks++) {
            uint32_t bfr[2][2];
            #pragma unroll
            for (int nt = 0; nt < 2; nt++) {
                int br = (wn*16 + nt*8 + g)*QST + ks*8 + t;
                bfr[nt][0] = K3s[br];
                bfr[nt][1] = K3s[br + 4];
            }
            #pragma unroll
            for (int nt = 0; nt < 2; nt++) {
                asm volatile(
                    "mma.sync.aligned.m16n8k16.row.col.f32.bf16.bf16.f32 "
                    "{%0,%1,%2,%3}, {%4,%5,%6,%7}, {%8,%9}, {%0,%1,%2,%3};"
                    : "+f"(sc[nt][0]), "+f"(sc[nt][1]), "+f"(sc[nt][2]), "+f"(sc[nt][3])
                    : "r"(qa[ks][0]), "r"(qa[ks][1]), "r"(qa[ks][2]), "r"(qa[ks][3]),
                      "r"(bfr[nt][0]), "r"(bfr[nt][1]));
            }
        }

        // --- softmax in fragments ---
        int r0 = wm*16 + g, r1 = r0 + 8;
        float mx0 = fmaxf(fmaxf(sc[0][0], sc[0][1]), fmaxf(sc[1][0], sc[1][1]));
        float mx1 = fmaxf(fmaxf(sc[0][2], sc[0][3]), fmaxf(sc[1][2], sc[1][3]));
        mx0 = fmaxf(mx0, __shfl_xor_sync(0xFFFFFFFFu, mx0, 1));
        mx0 = fmaxf(mx0, __shfl_xor_sync(0xFFFFFFFFu, mx0, 2));
        mx1 = fmaxf(mx1, __shfl_xor_sync(0xFFFFFFFFu, mx1, 1));
        mx1 = fmaxf(mx1, __shfl_xor_sync(0xFFFFFFFFu, mx1, 2));
        if (t == 0) { pmax[r0][wn] = mx0; pmax[r1][wn] = mx1; }
        __syncthreads();

        float M0 = fmaxf(fmaxf(pmax[r0][0], pmax[r0][1]), mrow[r0]);
        float M1 = fmaxf(fmaxf(pmax[r1][0], pmax[r1][1]), mrow[r1]);
        float s0 = 0.f, s1 = 0.f;
        #pragma unroll
        for (int nt = 0; nt < 2; nt++) {
            float p0 = __expf(sc[nt][0] - M0);
            float p1 = __expf(sc[nt][1] - M0);
            float p2 = __expf(sc[nt][2] - M1);
            float p3 = __expf(sc[nt][3] - M1);
            s0 += p0 + p1; s1 += p2 + p3;
            int c = wn*16 + nt*8 + 2*t;
            // split write: P3 = [Ph | Ph | Pl] over the 32-chunk
            __nv_bfloat16 h0 = __float2bfloat16(p0);
            __nv_bfloat16 l0 = __float2bfloat16(p0 - __bfloat162float(h0));
            __nv_bfloat16 h1 = __float2bfloat16(p1);
            __nv_bfloat16 l1 = __float2bfloat16(p1 - __bfloat162float(h1));
            __nv_bfloat16 h2 = __float2bfloat16(p2);
            __nv_bfloat16 l2 = __float2bfloat16(p2 - __bfloat162float(h2));
            __nv_bfloat16 h3 = __float2bfloat16(p3);
            __nv_bfloat16 l3 = __float2bfloat16(p3 - __bfloat162float(h3));
            P3h[r0*104 + c]      = h0;  P3h[r0*104 + c + 1]      = h1;
            P3h[r0*104 + 32 + c] = h0;  P3h[r0*104 + 32 + c + 1] = h1;
            P3h[r0*104 + 64 + c] = l0;  P3h[r0*104 + 64 + c + 1] = l1;
            P3h[r1*104 + c]      = h2;  P3h[r1*104 + c + 1]      = h3;
            P3h[r1*104 + 32 + c] = h2;  P3h[r1*104 + 32 + c + 1] = h3;
            P3h[r1*104 + 64 + c] = l2;  P3h[r1*104 + 64 + c + 1] = l3;
        }
        s0 += __shfl_xor_sync(0xFFFFFFFFu, s0, 1);
        s0 += __shfl_xor_sync(0xFFFFFFFFu, s0, 2);
        s1 += __shfl_xor_sync(0xFFFFFFFFu, s1, 1);
        s1 += __shfl_xor_sync(0xFFFFFFFFu, s1, 2);
        if (t == 0) { psum[r0][wn] = s0; psum[r1][wn] = s1; }
        __syncthreads();

        if (tid < 64) {
            float M = fmaxf(fmaxf(pmax[tid][0], pmax[tid][1]), mrow[tid]);
            float al = __expf(mrow[tid] - M);
            lrow[tid] = lrow[tid]*al + psum[tid][0] + psum[tid][1];
            arow[tid] = al;
            mrow[tid] = M;
        }
        __syncthreads();

        // --- O += P3 @ V3^T ---
        #pragma unroll
        for (int mt = 0; mt < 2; mt++) {
            int ra = wm2*32 + mt*16 + g;
            float a0 = arow[ra], a1 = arow[ra + 8];
            #pragma unroll
            for (int nt = 0; nt < 2; nt++) {
                o[mt][nt][0] *= a0; o[mt][nt][1] *= a0;
                o[mt][nt][2] *= a1; o[mt][nt][3] *= a1;
            }
        }
        #pragma unroll
        for (int ks = 0; ks < 6; ks++) {
            uint32_t pa[2][4], vb[2][2];
            #pragma unroll
            for (int mt = 0; mt < 2; mt++) {
                int ar = (wm2*32 + mt*16 + g)*VST + ks*8 + t;
                pa[mt][0] = P3s[ar];
                pa[mt][1] = P3s[ar + 8*VST];
                pa[mt][2] = P3s[ar + 4];
                pa[mt][3] = P3s[ar + 8*VST + 4];
            }
            #pragma unroll
            for (int nt = 0; nt < 2; nt++) {
                int br = (wn2*16 + nt*8 + g)*VST + ks*8 + t;
                vb[nt][0] = V3s[br];
                vb[nt][1] = V3s[br + 4];
            }
            #pragma unroll
            for (int mt = 0; mt < 2; mt++)
                #pragma unroll
                for (int nt = 0; nt < 2; nt++) {
                    asm volatile(
                        "mma.sync.aligned.m16n8k16.row.col.f32.bf16.bf16.f32 "
                        "{%0,%1,%2,%3}, {%4,%5,%6,%7}, {%8,%9}, {%0,%1,%2,%3};"
                        : "+f"(o[mt][nt][0]), "+f"(o[mt][nt][1]),
                          "+f"(o[mt][nt][2]), "+f"(o[mt][nt][3])
                        : "r"(pa[mt][0]), "r"(pa[mt][1]), "r"(pa[mt][2]), "r"(pa[mt][3]),
                          "r"(vb[nt][0]), "r"(vb[nt][1]));
                }
        }
        __syncthreads();
    }

    // epilogue: normalize, store to g_o [b*SQ+s][DM]
    int b = blockIdx.z, h = blockIdx.y;
    #pragma unroll
    for (int mt = 0; mt < 2; mt++) {
        int ra = wm2*32 + mt*16 + g;
        float i0 = 1.f / lrow[ra];
        float i1 = 1.f / lrow[ra + 8];
        #pragma unroll
        for (int nt = 0; nt < 2; nt++) {
            int col = wn2*16 + nt*8 + 2*t;
            float* Og0 = g_o + (size_t)(b*SQ + q0 + ra)*DM + h*64 + col;
            float* Og1 = g_o + (size_t)(b*SQ + q0 + ra + 8)*DM + h*64 + col;
            Og0[0] = o[mt][nt][0] * i0;
            Og0[1] = o[mt][nt][1] * i0;
            Og1[0] = o[mt][nt][2] * i1;
            Og1[1] = o[mt][nt][3] * i1;
        }
    }
}

extern "C" void kernel_launch(void* const* d_in, const int* in_sizes, int n_in,
                              void* d_out, int out_size)
{
    const float* x  = (const float*)d_in[0];
    const float* wq = (const float*)d_in[1];
    const float* bq = (const float*)d_in[2];
    const float* wk = (const float*)d_in[3];
    const float* bk = (const float*)d_in[4];
    const float* wv = (const float*)d_in[5];
    const float* bv = (const float*)d_in[6];
    const float* wo = (const float*)d_in[7];
    const float* bo = (const float*)d_in[8];
    float* out = (float*)d_out;

    float *q, *k, *v, *o;
    __nv_bfloat16 *x3, *o3, *wq3, *wk3, *wv3, *wo3;
    cudaGetSymbolAddress((void**)&q, g_q);
    cudaGetSymbolAddress((void**)&k, g_k);
    cudaGetSymbolAddress((void**)&v, g_v);
    cudaGetSymbolAddress((void**)&o, g_o);
    cudaGetSymbolAddress((void**)&x3, g_x3);
    cudaGetSymbolAddress((void**)&o3, g_o3);
    cudaGetSymbolAddress((void**)&wq3, g_wq3);
    cudaGetSymbolAddress((void**)&wk3, g_wk3);
    cudaGetSymbolAddress((void**)&wv3, g_wv3);
    cudaGetSymbolAddress((void**)&wo3, g_wo3);

    int eb = (MR*DM + 255)/256;
    dim3 tb(DM/32, DM/32);
    dim3 gg(DM/128, MR/128);

    expand_a3<<<eb, 256>>>(x, x3, MR, DM);
    expand_b3t<<<tb, 256>>>(wq, wq3, DM, DM);
    expand_b3t<<<tb, 256>>>(wk, wk3, DM, DM);
    expand_b3t<<<tb, 256>>>(wv, wv3, DM, DM);
    gemm_bf16<<<gg, 256>>>(x3, wq3, bq, q, MR, DM, K3);
    gemm_bf16<<<gg, 256>>>(x3, wk3, bk, k, MR, DM, K3);
    gemm_bf16<<<gg, 256>>>(x3, wv3, bv, v, MR, DM, K3);

    expand_q3k3<<<eb, 256>>>(q, k);
    expand_v3t<<<dim3(SQ/32, HD/32, BZ*HH), 256>>>(v);

    attn_mma<<<dim3(SQ/64, HH, BZ), 256>>>();

    expand_a3<<<eb, 256>>>(o, o3, MR, DM);
    expand_b3t<<<tb, 256>>>(wo, wo3, DM, DM);
    gemm_bf16<<<gg, 256>>>(o3, wo3, bo, out, MR, DM, K3);
}

// round 13
// speedup vs baseline: 5.0978x; 1.0418x over previous
#include <cuda_runtime.h>
#include <cuda_bf16.h>
#include <cstdint>
#include <math.h>

#define BZ   2
#define SQ   2048
#define DM   1024
#define HH   16
#define HD   64
#define MR   (BZ*SQ)      // 4096 rows
#define K3   (3*DM)       // 3072 expanded-K

// ---- device-global scratch (no allocations allowed) ----
__device__ float g_v[(size_t)MR*DM];
__device__ __align__(16) __nv_bfloat16 g_x3[(size_t)MR*K3];
__device__ __align__(16) __nv_bfloat16 g_o3[(size_t)MR*K3];
__device__ __align__(16) __nv_bfloat16 g_wq3[(size_t)DM*K3];   // [N][K3]
__device__ __align__(16) __nv_bfloat16 g_wk3[(size_t)DM*K3];
__device__ __align__(16) __nv_bfloat16 g_wv3[(size_t)DM*K3];
__device__ __align__(16) __nv_bfloat16 g_wo3[(size_t)DM*K3];
// attention split operands (per head):
__device__ __align__(16) __nv_bfloat16 g_q3[(size_t)BZ*HH*SQ*192];     // [bh][s][h|h|l]
__device__ __align__(16) __nv_bfloat16 g_k3[(size_t)BZ*HH*SQ*192];     // [bh][s][h|l|h]
__device__ __align__(16) __nv_bfloat16 g_v3t[(size_t)BZ*HH*HD*3*SQ];   // [bh][hd][Vh|Vl|Vh over s]

// ---------------------------------------------------------------------------
// Split expansions (x -> x3, weights -> transposed [N][3K])
// ---------------------------------------------------------------------------
__global__ __launch_bounds__(256) void expand_a3(
    const float* __restrict__ src, __nv_bfloat16* __restrict__ dst, int M, int K)
{
    int idx = blockIdx.x*256 + threadIdx.x;
    if (idx >= M*K) return;
    int m = idx / K, k = idx - m*K;
    float x = src[idx];
    __nv_bfloat16 h = __float2bfloat16(x);
    __nv_bfloat16 l = __float2bfloat16(x - __bfloat162float(h));
    size_t base = (size_t)m*3*K;
    dst[base + k] = h;
    dst[base + K + k] = h;
    dst[base + 2*K + k] = l;
}

__global__ __launch_bounds__(256) void expand_b3t(
    const float* __restrict__ src, __nv_bfloat16* __restrict__ dst, int K, int N)
{
    __shared__ float t[32][33];
    int tx = threadIdx.x & 31, ty = threadIdx.x >> 5;
    int nb = blockIdx.x * 32, kb = blockIdx.y * 32;
    #pragma unroll
    for (int i = 0; i < 4; i++)
        t[ty + 8*i][tx] = src[(size_t)(kb + ty + 8*i)*N + nb + tx];
    __syncthreads();
    #pragma unroll
    for (int i = 0; i < 4; i++) {
        int n = nb + ty + 8*i;
        int k = kb + tx;
        float x = t[tx][ty + 8*i];
        __nv_bfloat16 h = __float2bfloat16(x);
        __nv_bfloat16 l = __float2bfloat16(x - __bfloat162float(h));
        size_t base = (size_t)n*3*K;
        dst[base + k]       = h;
        dst[base + K + k]   = l;
        dst[base + 2*K + k] = h;
    }
}

// V transpose-expand: per (b,h): dst [hd][3*SQ] = [Vh | Vl | Vh] over s
__global__ __launch_bounds__(256) void expand_v3t(const float* __restrict__ src)
{
    __shared__ float t[32][33];
    int tx = threadIdx.x & 31, ty = threadIdx.x >> 5;
    int s0 = blockIdx.x * 32;
    int hd0 = blockIdx.y * 32;
    int bh = blockIdx.z;
    int b = bh >> 4, h = bh & 15;
    #pragma unroll
    for (int i = 0; i < 4; i++)
        t[ty + 8*i][tx] = src[(size_t)(b*SQ + s0 + ty + 8*i)*DM + h*64 + hd0 + tx];
    __syncthreads();
    #pragma unroll
    for (int i = 0; i < 4; i++) {
        int hd = hd0 + ty + 8*i;
        float x = t[tx][ty + 8*i];
        __nv_bfloat16 hh = __float2bfloat16(x);
        __nv_bfloat16 ll = __float2bfloat16(x - __bfloat162float(hh));
        size_t base = ((size_t)bh*HD + hd)*3*SQ;
        g_v3t[base + s0 + tx]        = hh;
        g_v3t[base + SQ + s0 + tx]   = ll;
        g_v3t[base + 2*SQ + s0 + tx] = hh;
    }
}

// ---------------------------------------------------------------------------
// bf16 HMMA GEMM v5: cp.async double-buffered (no register staging).
// mode 0: C = fp32 (acc+bias). mode 1: split [h|h|l] into g_q3 (x0.125).
// mode 2: split [h|l|h] into g_k3.
// ---------------------------------------------------------------------------
#define AST 20
#define STG (128*AST)

__global__ __launch_bounds__(256) void gemm_bf16(
    const __nv_bfloat16* __restrict__ A, const __nv_bfloat16* __restrict__ Bt,
    const float* __restrict__ bias, void* __restrict__ Cv,
    int M, int N, int Kx, int mode)
{
    __shared__ __align__(16) uint32_t As[2*STG];   // 20 KB
    __shared__ __align__(16) uint32_t Bs[2*STG];   // 20 KB

    int tid = threadIdx.x;
    int lane = tid & 31;
    int w = tid >> 5;
    int wm = w >> 2;
    int wn = w & 3;
    int g = lane >> 2;
    int t = lane & 3;

    int m0 = blockIdx.y * 128;
    int n0 = blockIdx.x * 128;

    const int r0 = tid >> 2,  c0 = tid & 3;
    const int r1 = r0 + 64,   c1 = c0;

    const __nv_bfloat16* pA0 = A  + (size_t)(m0 + r0)*Kx + c0*8;
    const __nv_bfloat16* pA1 = A  + (size_t)(m0 + r1)*Kx + c1*8;
    const __nv_bfloat16* pB0 = Bt + (size_t)(n0 + r0)*Kx + c0*8;
    const __nv_bfloat16* pB1 = Bt + (size_t)(n0 + r1)*Kx + c1*8;

    uint32_t sA = (uint32_t)__cvta_generic_to_shared(As);
    uint32_t sB = (uint32_t)__cvta_generic_to_shared(Bs);
    uint32_t dA0 = sA + (r0*AST + c0*4)*4;
    uint32_t dA1 = sA + (r1*AST + c1*4)*4;
    uint32_t dB0 = sB + (r0*AST + c0*4)*4;
    uint32_t dB1 = sB + (r1*AST + c1*4)*4;

    float acc[4][4][4];
    #pragma unroll
    for (int i = 0; i < 4; i++)
        #pragma unroll
        for (int j = 0; j < 4; j++)
            #pragma unroll
            for (int r = 0; r < 4; r++) acc[i][j][r] = 0.f;

    const int NC = Kx >> 5;   // 96

    // prologue: chunk 0 -> stage 0
    asm volatile("cp.async.cg.shared.global [%0], [%1], 16;\n" :: "r"(dA0), "l"(pA0));
    asm volatile("cp.async.cg.shared.global [%0], [%1], 16;\n" :: "r"(dA1), "l"(pA1));
    asm volatile("cp.async.cg.shared.global [%0], [%1], 16;\n" :: "r"(dB0), "l"(pB0));
    asm volatile("cp.async.cg.shared.global [%0], [%1], 16;\n" :: "r"(dB1), "l"(pB1));
    asm volatile("cp.async.commit_group;\n");

    for (int c = 0; c < NC; c++) {
        const int s = c & 1;
        const int sn = s ^ 1;
        asm volatile("cp.async.wait_group 0;\n");
        __syncthreads();   // stage s ready; all warps done with stage sn

        if (c + 1 < NC) {
            int ko = (c + 1) << 5;
            uint32_t off = sn*STG*4;
            asm volatile("cp.async.cg.shared.global [%0], [%1], 16;\n"
                         :: "r"(dA0 + off), "l"(pA0 + ko));
            asm volatile("cp.async.cg.shared.global [%0], [%1], 16;\n"
                         :: "r"(dA1 + off), "l"(pA1 + ko));
            asm volatile("cp.async.cg.shared.global [%0], [%1], 16;\n"
                         :: "r"(dB0 + off), "l"(pB0 + ko));
            asm volatile("cp.async.cg.shared.global [%0], [%1], 16;\n"
                         :: "r"(dB1 + off), "l"(pB1 + ko));
            asm volatile("cp.async.commit_group;\n");
        }

        const uint32_t* Ab = As + s*STG;
        const uint32_t* Bb = Bs + s*STG;

        #pragma unroll
        for (int ss = 0; ss < 2; ss++) {
            uint32_t a[4][4], b[4][2];
            #pragma unroll
            for (int mt = 0; mt < 4; mt++) {
                int ar = (wm*64 + mt*16 + g)*AST + ss*8 + t;
                a[mt][0] = Ab[ar];
                a[mt][1] = Ab[ar + 8*AST];
                a[mt][2] = Ab[ar + 4];
                a[mt][3] = Ab[ar + 8*AST + 4];
            }
            #pragma unroll
            for (int nt = 0; nt < 4; nt++) {
                int br = (wn*32 + nt*8 + g)*AST + ss*8 + t;
                b[nt][0] = Bb[br];
                b[nt][1] = Bb[br + 4];
            }
            #pragma unroll
            for (int mt = 0; mt < 4; mt++)
                #pragma unroll
                for (int nt = 0; nt < 4; nt++) {
                    asm volatile(
                        "mma.sync.aligned.m16n8k16.row.col.f32.bf16.bf16.f32 "
                        "{%0,%1,%2,%3}, {%4,%5,%6,%7}, {%8,%9}, {%0,%1,%2,%3};"
                        : "+f"(acc[mt][nt][0]), "+f"(acc[mt][nt][1]),
                          "+f"(acc[mt][nt][2]), "+f"(acc[mt][nt][3])
                        : "r"(a[mt][0]), "r"(a[mt][1]), "r"(a[mt][2]), "r"(a[mt][3]),
                          "r"(b[nt][0]), "r"(b[nt][1]));
                }
        }
    }

    if (mode == 0) {
        float* C = (float*)Cv;
        #pragma unroll
        for (int mt = 0; mt < 4; mt++) {
            int row0 = m0 + wm*64 + mt*16 + g;
            #pragma unroll
            for (int nt = 0; nt < 4; nt++) {
                int col = n0 + wn*32 + nt*8 + 2*t;
                float b0 = bias[col], b1 = bias[col+1];
                C[(size_t)row0*N + col]         = acc[mt][nt][0] + b0;
                C[(size_t)row0*N + col + 1]     = acc[mt][nt][1] + b1;
                C[(size_t)(row0+8)*N + col]     = acc[mt][nt][2] + b0;
                C[(size_t)(row0+8)*N + col + 1] = acc[mt][nt][3] + b1;
            }
        }
    } else {
        // split-write into g_q3 / g_k3 layout [bh][s][192]
        __nv_bfloat16* D = (__nv_bfloat16*)Cv;
        float sc = (mode == 1) ? 0.125f : 1.0f;
        #pragma unroll
        for (int mt = 0; mt < 4; mt++) {
            int row0 = m0 + wm*64 + mt*16 + g;
            #pragma unroll
            for (int nt = 0; nt < 4; nt++) {
                int col = n0 + wn*32 + nt*8 + 2*t;
                float b0 = bias[col], b1 = bias[col+1];
                #pragma unroll
                for (int half = 0; half < 2; half++) {
                    int row = row0 + half*8;
                    int bb = row >> 11, s = row & 2047;
                    int hh = col >> 6, hd = col & 63;
                    size_t base = ((size_t)(bb*HH + hh)*SQ + s)*192;
                    float v0 = (acc[mt][nt][half*2]     + b0) * sc;
                    float v1 = (acc[mt][nt][half*2 + 1] + b1) * sc;
                    __nv_bfloat16 h0 = __float2bfloat16(v0);
                    __nv_bfloat16 l0 = __float2bfloat16(v0 - __bfloat162float(h0));
                    __nv_bfloat16 h1 = __float2bfloat16(v1);
                    __nv_bfloat16 l1 = __float2bfloat16(v1 - __bfloat162float(h1));
                    if (mode == 1) {   // Q: [h|h|l]
                        D[base + hd] = h0;       D[base + hd + 1] = h1;
                        D[base + 64 + hd] = h0;  D[base + 64 + hd + 1] = h1;
                        D[base + 128 + hd] = l0; D[base + 128 + hd + 1] = l1;
                    } else {           // K: [h|l|h]
                        D[base + hd] = h0;       D[base + hd + 1] = h1;
                        D[base + 64 + hd] = l0;  D[base + 64 + hd + 1] = l1;
                        D[base + 128 + hd] = h0; D[base + 128 + hd + 1] = h1;
                    }
                }
            }
        }
    }
}

// ---------------------------------------------------------------------------
// HMMA flash attention with 3-term split (unchanged core from R12).
// Epilogue now writes g_o3 ([h|h|l] over DM) directly.
// ---------------------------------------------------------------------------
#define QST 100
#define VST 52

__global__ __launch_bounds__(256) void attn_mma()
{
    __shared__ __align__(16) uint32_t U[6656];
    __shared__ __align__(16) uint32_t K3s[32*QST];
    __shared__ float mrow[64], lrow[64], arow[64];
    __shared__ float pmax[64][2], psum[64][2];

    int tid = threadIdx.x, lane = tid & 31, w = tid >> 5;
    int g = lane >> 2, t = lane & 3;
    int q0 = blockIdx.x * 64;
    int bh = blockIdx.z * HH + blockIdx.y;

    int wm = w >> 1, wn = w & 1;
    int wm2 = w >> 2, wn2 = w & 3;

    const __nv_bfloat16* Qg = g_q3 + ((size_t)bh*SQ + q0)*192;
    #pragma unroll
    for (int i = 0; i < 6; i++) {
        int idx = tid + i*256;
        int r = idx / 24, c = idx % 24;
        *(uint4*)&U[r*QST + c*4] = *(const uint4*)(Qg + (size_t)r*192 + c*8);
    }
    if (tid < 64) { mrow[tid] = -INFINITY; lrow[tid] = 0.f; }
    __syncthreads();

    uint32_t qa[12][4];
    #pragma unroll
    for (int ks = 0; ks < 12; ks++) {
        int ar = (wm*16 + g)*QST + ks*8 + t;
        qa[ks][0] = U[ar];
        qa[ks][1] = U[ar + 8*QST];
        qa[ks][2] = U[ar + 4];
        qa[ks][3] = U[ar + 8*QST + 4];
    }
    __syncthreads();

    uint32_t* V3s = U;
    uint32_t* P3s = U + 3328;
    __nv_bfloat16* P3h = (__nv_bfloat16*)P3s;

    float o[2][2][4] = {};

    const __nv_bfloat16* Kg = g_k3 + (size_t)bh*SQ*192;
    const __nv_bfloat16* Vg = g_v3t + (size_t)bh*HD*3*SQ;

    for (int k0 = 0; k0 < SQ; k0 += 32) {
        #pragma unroll
        for (int i = 0; i < 3; i++) {
            int idx = tid + i*256;
            int r = idx / 24, c = idx % 24;
            *(uint4*)&K3s[r*QST + c*4] = *(const uint4*)(Kg + (size_t)(k0+r)*192 + c*8);
        }
        #pragma unroll
        for (int i = 0; i < 3; i++) {
            int idx = tid + i*256;
            int r = idx / 12, sub = idx % 12;
            int blk = sub >> 2, c = sub & 3;
            *(uint4*)&V3s[r*VST + blk*16 + c*4] =
                *(const uint4*)(Vg + (size_t)r*3*SQ + blk*SQ + k0 + c*8);
        }
        __syncthreads();

        float sc[2][4];
        #pragma unroll
        for (int nt = 0; nt < 2; nt++)
            #pragma unroll
            for (int r = 0; r < 4; r++) sc[nt][r] = 0.f;
        #pragma unroll
        for (int ks = 0; ks < 12; ks++) {
            uint32_t bfr[2][2];
            #pragma unroll
            for (int nt = 0; nt < 2; nt++) {
                int br = (wn*16 + nt*8 + g)*QST + ks*8 + t;
                bfr[nt][0] = K3s[br];
                bfr[nt][1] = K3s[br + 4];
            }
            #pragma unroll
            for (int nt = 0; nt < 2; nt++) {
                asm volatile(
                    "mma.sync.aligned.m16n8k16.row.col.f32.bf16.bf16.f32 "
                    "{%0,%1,%2,%3}, {%4,%5,%6,%7}, {%8,%9}, {%0,%1,%2,%3};"
                    : "+f"(sc[nt][0]), "+f"(sc[nt][1]), "+f"(sc[nt][2]), "+f"(sc[nt][3])
                    : "r"(qa[ks][0]), "r"(qa[ks][1]), "r"(qa[ks][2]), "r"(qa[ks][3]),
                      "r"(bfr[nt][0]), "r"(bfr[nt][1]));
            }
        }

        int r0 = wm*16 + g, r1 = r0 + 8;
        float mx0 = fmaxf(fmaxf(sc[0][0], sc[0][1]), fmaxf(sc[1][0], sc[1][1]));
        float mx1 = fmaxf(fmaxf(sc[0][2], sc[0][3]), fmaxf(sc[1][2], sc[1][3]));
        mx0 = fmaxf(mx0, __shfl_xor_sync(0xFFFFFFFFu, mx0, 1));
        mx0 = fmaxf(mx0, __shfl_xor_sync(0xFFFFFFFFu, mx0, 2));
        mx1 = fmaxf(mx1, __shfl_xor_sync(0xFFFFFFFFu, mx1, 1));
        mx1 = fmaxf(mx1, __shfl_xor_sync(0xFFFFFFFFu, mx1, 2));
        if (t == 0) { pmax[r0][wn] = mx0; pmax[r1][wn] = mx1; }
        __syncthreads();

        float M0 = fmaxf(fmaxf(pmax[r0][0], pmax[r0][1]), mrow[r0]);
        float M1 = fmaxf(fmaxf(pmax[r1][0], pmax[r1][1]), mrow[r1]);
        float s0 = 0.f, s1 = 0.f;
        #pragma unroll
        for (int nt = 0; nt < 2; nt++) {
            float p0 = __expf(sc[nt][0] - M0);
            float p1 = __expf(sc[nt][1] - M0);
            float p2 = __expf(sc[nt][2] - M1);
            float p3 = __expf(sc[nt][3] - M1);
            s0 += p0 + p1; s1 += p2 + p3;
            int c = wn*16 + nt*8 + 2*t;
            __nv_bfloat16 h0 = __float2bfloat16(p0);
            __nv_bfloat16 l0 = __float2bfloat16(p0 - __bfloat162float(h0));
            __nv_bfloat16 h1 = __float2bfloat16(p1);
            __nv_bfloat16 l1 = __float2bfloat16(p1 - __bfloat162float(h1));
            __nv_bfloat16 h2 = __float2bfloat16(p2);
            __nv_bfloat16 l2 = __float2bfloat16(p2 - __bfloat162float(h2));
            __nv_bfloat16 h3 = __float2bfloat16(p3);
            __nv_bfloat16 l3 = __float2bfloat16(p3 - __bfloat162float(h3));
            P3h[r0*104 + c]      = h0;  P3h[r0*104 + c + 1]      = h1;
            P3h[r0*104 + 32 + c] = h0;  P3h[r0*104 + 32 + c + 1] = h1;
            P3h[r0*104 + 64 + c] = l0;  P3h[r0*104 + 64 + c + 1] = l1;
            P3h[r1*104 + c]      = h2;  P3h[r1*104 + c + 1]      = h3;
            P3h[r1*104 + 32 + c] = h2;  P3h[r1*104 + 32 + c + 1] = h3;
            P3h[r1*104 + 64 + c] = l2;  P3h[r1*104 + 64 + c + 1] = l3;
        }
        s0 += __shfl_xor_sync(0xFFFFFFFFu, s0, 1);
        s0 += __shfl_xor_sync(0xFFFFFFFFu, s0, 2);
        s1 += __shfl_xor_sync(0xFFFFFFFFu, s1, 1);
        s1 += __shfl_xor_sync(0xFFFFFFFFu, s1, 2);
        if (t == 0) { psum[r0][wn] = s0; psum[r1][wn] = s1; }
        __syncthreads();

        if (tid < 64) {
            float M = fmaxf(fmaxf(pmax[tid][0], pmax[tid][1]), mrow[tid]);
            float al = __expf(mrow[tid] - M);
            lrow[tid] = lrow[tid]*al + psum[tid][0] + psum[tid][1];
            arow[tid] = al;
            mrow[tid] = M;
        }
        __syncthreads();

        #pragma unroll
        for (int mt = 0; mt < 2; mt++) {
            int ra = wm2*32 + mt*16 + g;
            float a0 = arow[ra], a1 = arow[ra + 8];
            #pragma unroll
            for (int nt = 0; nt < 2; nt++) {
                o[mt][nt][0] *= a0; o[mt][nt][1] *= a0;
                o[mt][nt][2] *= a1; o[mt][nt][3] *= a1;
            }
        }
        #pragma unroll
        for (int ks = 0; ks < 6; ks++) {
            uint32_t pa[2][4], vb[2][2];
            #pragma unroll
            for (int mt = 0; mt < 2; mt++) {
                int ar = (wm2*32 + mt*16 + g)*VST + ks*8 + t;
                pa[mt][0] = P3s[ar];
                pa[mt][1] = P3s[ar + 8*VST];
                pa[mt][2] = P3s[ar + 4];
                pa[mt][3] = P3s[ar + 8*VST + 4];
            }
            #pragma unroll
            for (int nt = 0; nt < 2; nt++) {
                int br = (wn2*16 + nt*8 + g)*VST + ks*8 + t;
                vb[nt][0] = V3s[br];
                vb[nt][1] = V3s[br + 4];
            }
            #pragma unroll
            for (int mt = 0; mt < 2; mt++)
                #pragma unroll
                for (int nt = 0; nt < 2; nt++) {
                    asm volatile(
                        "mma.sync.aligned.m16n8k16.row.col.f32.bf16.bf16.f32 "
                        "{%0,%1,%2,%3}, {%4,%5,%6,%7}, {%8,%9}, {%0,%1,%2,%3};"
                        : "+f"(o[mt][nt][0]), "+f"(o[mt][nt][1]),
                          "+f"(o[mt][nt][2]), "+f"(o[mt][nt][3])
                        : "r"(pa[mt][0]), "r"(pa[mt][1]), "r"(pa[mt][2]), "r"(pa[mt][3]),
                          "r"(vb[nt][0]), "r"(vb[nt][1]));
                }
        }
        __syncthreads();
    }

    // epilogue: normalize + split-write g_o3 ([h|h|l] over DM=1024)
    int b = blockIdx.z, h = blockIdx.y;
    #pragma unroll
    for (int mt = 0; mt < 2; mt++) {
        int ra = wm2*32 + mt*16 + g;
        float i0 = 1.f / lrow[ra];
        float i1 = 1.f / lrow[ra + 8];
        #pragma unroll
        for (int nt = 0; nt < 2; nt++) {
            int col = h*64 + wn2*16 + nt*8 + 2*t;
            size_t b0 = (size_t)(b*SQ + q0 + ra)*K3;
            size_t b1 = (size_t)(b*SQ + q0 + ra + 8)*K3;
            float v00 = o[mt][nt][0] * i0, v01 = o[mt][nt][1] * i0;
            float v10 = o[mt][nt][2] * i1, v11 = o[mt][nt][3] * i1;
            __nv_bfloat16 h00 = __float2bfloat16(v00);
            __nv_bfloat16 l00 = __float2bfloat16(v00 - __bfloat162float(h00));
            __nv_bfloat16 h01 = __float2bfloat16(v01);
            __nv_bfloat16 l01 = __float2bfloat16(v01 - __bfloat162float(h01));
            __nv_bfloat16 h10 = __float2bfloat16(v10);
            __nv_bfloat16 l10 = __float2bfloat16(v10 - __bfloat162float(h10));
            __nv_bfloat16 h11 = __float2bfloat16(v11);
            __nv_bfloat16 l11 = __float2bfloat16(v11 - __bfloat162float(h11));
            g_o3[b0 + col] = h00;          g_o3[b0 + col + 1] = h01;
            g_o3[b0 + DM + col] = h00;     g_o3[b0 + DM + col + 1] = h01;
            g_o3[b0 + 2*DM + col] = l00;   g_o3[b0 + 2*DM + col + 1] = l01;
            g_o3[b1 + col] = h10;          g_o3[b1 + col + 1] = h11;
            g_o3[b1 + DM + col] = h10;     g_o3[b1 + DM + col + 1] = h11;
            g_o3[b1 + 2*DM + col] = l10;   g_o3[b1 + 2*DM + col + 1] = l11;
        }
    }
}

extern "C" void kernel_launch(void* const* d_in, const int* in_sizes, int n_in,
                              void* d_out, int out_size)
{
    const float* x  = (const float*)d_in[0];
    const float* wq = (const float*)d_in[1];
    const float* bq = (const float*)d_in[2];
    const float* wk = (const float*)d_in[3];
    const float* bk = (const float*)d_in[4];
    const float* wv = (const float*)d_in[5];
    const float* bv = (const float*)d_in[6];
    const float* wo = (const float*)d_in[7];
    const float* bo = (const float*)d_in[8];
    float* out = (float*)d_out;

    float *v;
    __nv_bfloat16 *x3, *o3, *wq3, *wk3, *wv3, *wo3, *q3, *k3;
    cudaGetSymbolAddress((void**)&v, g_v);
    cudaGetSymbolAddress((void**)&x3, g_x3);
    cudaGetSymbolAddress((void**)&o3, g_o3);
    cudaGetSymbolAddress((void**)&wq3, g_wq3);
    cudaGetSymbolAddress((void**)&wk3, g_wk3);
    cudaGetSymbolAddress((void**)&wv3, g_wv3);
    cudaGetSymbolAddress((void**)&wo3, g_wo3);
    cudaGetSymbolAddress((void**)&q3, g_q3);
    cudaGetSymbolAddress((void**)&k3, g_k3);

    int eb = (MR*DM + 255)/256;
    dim3 tb(DM/32, DM/32);
    dim3 gg(DM/128, MR/128);

    expand_a3<<<eb, 256>>>(x, x3, MR, DM);
    expand_b3t<<<tb, 256>>>(wq, wq3, DM, DM);
    expand_b3t<<<tb, 256>>>(wk, wk3, DM, DM);
    expand_b3t<<<tb, 256>>>(wv, wv3, DM, DM);
    gemm_bf16<<<gg, 256>>>(x3, wq3, bq, q3, MR, DM, K3, 1);  // Q split, scaled
    gemm_bf16<<<gg, 256>>>(x3, wk3, bk, k3, MR, DM, K3, 2);  // K split
    gemm_bf16<<<gg, 256>>>(x3, wv3, bv, v,  MR, DM, K3, 0);  // V fp32

    expand_v3t<<<dim3(SQ/32, HD/32, BZ*HH), 256>>>(v);

    attn_mma<<<dim3(SQ/64, HH, BZ), 256>>>();                // writes g_o3

    expand_b3t<<<tb, 256>>>(wo, wo3, DM, DM);
    gemm_bf16<<<gg, 256>>>(o3, wo3, bo, out, MR, DM, K3, 0);
}

// round 14
// speedup vs baseline: 5.3468x; 1.0488x over previous
#include <cuda_runtime.h>
#include <cuda_bf16.h>
#include <cstdint>
#include <math.h>

#define BZ   2
#define SQ   2048
#define DM   1024
#define HH   16
#define HD   64
#define MR   (BZ*SQ)      // 4096 rows
#define K3   (3*DM)       // 3072 expanded-K

// ---- device-global scratch (no allocations allowed) ----
__device__ float g_v[(size_t)MR*DM];
__device__ __align__(16) __nv_bfloat16 g_x3[(size_t)MR*K3];
__device__ __align__(16) __nv_bfloat16 g_o3[(size_t)MR*K3];
__device__ __align__(16) __nv_bfloat16 g_wq3[(size_t)DM*K3];   // [N][K3]
__device__ __align__(16) __nv_bfloat16 g_wk3[(size_t)DM*K3];
__device__ __align__(16) __nv_bfloat16 g_wv3[(size_t)DM*K3];
__device__ __align__(16) __nv_bfloat16 g_wo3[(size_t)DM*K3];
// attention split operands (per head):
__device__ __align__(16) __nv_bfloat16 g_q3[(size_t)BZ*HH*SQ*192];     // [bh][s][h|h|l]
__device__ __align__(16) __nv_bfloat16 g_k3[(size_t)BZ*HH*SQ*192];     // [bh][s][h|l|h]
__device__ __align__(16) __nv_bfloat16 g_v3t[(size_t)BZ*HH*HD*3*SQ];   // [bh][hd][Vh|Vl|Vh over s]

// ---------------------------------------------------------------------------
// Split expansions
// ---------------------------------------------------------------------------
__global__ __launch_bounds__(256) void expand_a3(
    const float* __restrict__ src, __nv_bfloat16* __restrict__ dst, int M, int K)
{
    int idx = blockIdx.x*256 + threadIdx.x;
    if (idx >= M*K) return;
    int m = idx / K, k = idx - m*K;
    float x = src[idx];
    __nv_bfloat16 h = __float2bfloat16(x);
    __nv_bfloat16 l = __float2bfloat16(x - __bfloat162float(h));
    size_t base = (size_t)m*3*K;
    dst[base + k] = h;
    dst[base + K + k] = h;
    dst[base + 2*K + k] = l;
}

__global__ __launch_bounds__(256) void expand_b3t(
    const float* __restrict__ src, __nv_bfloat16* __restrict__ dst, int K, int N)
{
    __shared__ float t[32][33];
    int tx = threadIdx.x & 31, ty = threadIdx.x >> 5;
    int nb = blockIdx.x * 32, kb = blockIdx.y * 32;
    #pragma unroll
    for (int i = 0; i < 4; i++)
        t[ty + 8*i][tx] = src[(size_t)(kb + ty + 8*i)*N + nb + tx];
    __syncthreads();
    #pragma unroll
    for (int i = 0; i < 4; i++) {
        int n = nb + ty + 8*i;
        int k = kb + tx;
        float x = t[tx][ty + 8*i];
        __nv_bfloat16 h = __float2bfloat16(x);
        __nv_bfloat16 l = __float2bfloat16(x - __bfloat162float(h));
        size_t base = (size_t)n*3*K;
        dst[base + k]       = h;
        dst[base + K + k]   = l;
        dst[base + 2*K + k] = h;
    }
}

__global__ __launch_bounds__(256) void expand_v3t(const float* __restrict__ src)
{
    __shared__ float t[32][33];
    int tx = threadIdx.x & 31, ty = threadIdx.x >> 5;
    int s0 = blockIdx.x * 32;
    int hd0 = blockIdx.y * 32;
    int bh = blockIdx.z;
    int b = bh >> 4, h = bh & 15;
    #pragma unroll
    for (int i = 0; i < 4; i++)
        t[ty + 8*i][tx] = src[(size_t)(b*SQ + s0 + ty + 8*i)*DM + h*64 + hd0 + tx];
    __syncthreads();
    #pragma unroll
    for (int i = 0; i < 4; i++) {
        int hd = hd0 + ty + 8*i;
        float x = t[tx][ty + 8*i];
        __nv_bfloat16 hh = __float2bfloat16(x);
        __nv_bfloat16 ll = __float2bfloat16(x - __bfloat162float(hh));
        size_t base = ((size_t)bh*HD + hd)*3*SQ;
        g_v3t[base + s0 + tx]        = hh;
        g_v3t[base + SQ + s0 + tx]   = ll;
        g_v3t[base + 2*SQ + s0 + tx] = hh;
    }
}

// ---------------------------------------------------------------------------
// bf16 HMMA GEMM v5 (unchanged from R13, proven): cp.async double-buffered.
// mode 0: fp32 out. mode 1: split [h|h|l] -> g_q3 (x0.125). mode 2: [h|l|h] -> g_k3.
// ---------------------------------------------------------------------------
#define AST 20
#define STG (128*AST)

__global__ __launch_bounds__(256) void gemm_bf16(
    const __nv_bfloat16* __restrict__ A, const __nv_bfloat16* __restrict__ Bt,
    const float* __restrict__ bias, void* __restrict__ Cv,
    int M, int N, int Kx, int mode)
{
    __shared__ __align__(16) uint32_t As[2*STG];
    __shared__ __align__(16) uint32_t Bs[2*STG];

    int tid = threadIdx.x;
    int lane = tid & 31;
    int w = tid >> 5;
    int wm = w >> 2;
    int wn = w & 3;
    int g = lane >> 2;
    int t = lane & 3;

    int m0 = blockIdx.y * 128;
    int n0 = blockIdx.x * 128;

    const int r0 = tid >> 2,  c0 = tid & 3;
    const int r1 = r0 + 64,   c1 = c0;

    const __nv_bfloat16* pA0 = A  + (size_t)(m0 + r0)*Kx + c0*8;
    const __nv_bfloat16* pA1 = A  + (size_t)(m0 + r1)*Kx + c1*8;
    const __nv_bfloat16* pB0 = Bt + (size_t)(n0 + r0)*Kx + c0*8;
    const __nv_bfloat16* pB1 = Bt + (size_t)(n0 + r1)*Kx + c1*8;

    uint32_t sA = (uint32_t)__cvta_generic_to_shared(As);
    uint32_t sB = (uint32_t)__cvta_generic_to_shared(Bs);
    uint32_t dA0 = sA + (r0*AST + c0*4)*4;
    uint32_t dA1 = sA + (r1*AST + c1*4)*4;
    uint32_t dB0 = sB + (r0*AST + c0*4)*4;
    uint32_t dB1 = sB + (r1*AST + c1*4)*4;

    float acc[4][4][4];
    #pragma unroll
    for (int i = 0; i < 4; i++)
        #pragma unroll
        for (int j = 0; j < 4; j++)
            #pragma unroll
            for (int r = 0; r < 4; r++) acc[i][j][r] = 0.f;

    const int NC = Kx >> 5;

    asm volatile("cp.async.cg.shared.global [%0], [%1], 16;\n" :: "r"(dA0), "l"(pA0));
    asm volatile("cp.async.cg.shared.global [%0], [%1], 16;\n" :: "r"(dA1), "l"(pA1));
    asm volatile("cp.async.cg.shared.global [%0], [%1], 16;\n" :: "r"(dB0), "l"(pB0));
    asm volatile("cp.async.cg.shared.global [%0], [%1], 16;\n" :: "r"(dB1), "l"(pB1));
    asm volatile("cp.async.commit_group;\n");

    for (int c = 0; c < NC; c++) {
        const int s = c & 1;
        const int sn = s ^ 1;
        asm volatile("cp.async.wait_group 0;\n");
        __syncthreads();

        if (c + 1 < NC) {
            int ko = (c + 1) << 5;
            uint32_t off = sn*STG*4;
            asm volatile("cp.async.cg.shared.global [%0], [%1], 16;\n"
                         :: "r"(dA0 + off), "l"(pA0 + ko));
            asm volatile("cp.async.cg.shared.global [%0], [%1], 16;\n"
                         :: "r"(dA1 + off), "l"(pA1 + ko));
            asm volatile("cp.async.cg.shared.global [%0], [%1], 16;\n"
                         :: "r"(dB0 + off), "l"(pB0 + ko));
            asm volatile("cp.async.cg.shared.global [%0], [%1], 16;\n"
                         :: "r"(dB1 + off), "l"(pB1 + ko));
            asm volatile("cp.async.commit_group;\n");
        }

        const uint32_t* Ab = As + s*STG;
        const uint32_t* Bb = Bs + s*STG;

        #pragma unroll
        for (int ss = 0; ss < 2; ss++) {
            uint32_t a[4][4], b[4][2];
            #pragma unroll
            for (int mt = 0; mt < 4; mt++) {
                int ar = (wm*64 + mt*16 + g)*AST + ss*8 + t;
                a[mt][0] = Ab[ar];
                a[mt][1] = Ab[ar + 8*AST];
                a[mt][2] = Ab[ar + 4];
                a[mt][3] = Ab[ar + 8*AST + 4];
            }
            #pragma unroll
            for (int nt = 0; nt < 4; nt++) {
                int br = (wn*32 + nt*8 + g)*AST + ss*8 + t;
                b[nt][0] = Bb[br];
                b[nt][1] = Bb[br + 4];
            }
            #pragma unroll
            for (int mt = 0; mt < 4; mt++)
                #pragma unroll
                for (int nt = 0; nt < 4; nt++) {
                    asm volatile(
                        "mma.sync.aligned.m16n8k16.row.col.f32.bf16.bf16.f32 "
                        "{%0,%1,%2,%3}, {%4,%5,%6,%7}, {%8,%9}, {%0,%1,%2,%3};"
                        : "+f"(acc[mt][nt][0]), "+f"(acc[mt][nt][1]),
                          "+f"(acc[mt][nt][2]), "+f"(acc[mt][nt][3])
                        : "r"(a[mt][0]), "r"(a[mt][1]), "r"(a[mt][2]), "r"(a[mt][3]),
                          "r"(b[nt][0]), "r"(b[nt][1]));
                }
        }
    }

    if (mode == 0) {
        float* C = (float*)Cv;
        #pragma unroll
        for (int mt = 0; mt < 4; mt++) {
            int row0 = m0 + wm*64 + mt*16 + g;
            #pragma unroll
            for (int nt = 0; nt < 4; nt++) {
                int col = n0 + wn*32 + nt*8 + 2*t;
                float b0 = bias[col], b1 = bias[col+1];
                C[(size_t)row0*N + col]         = acc[mt][nt][0] + b0;
                C[(size_t)row0*N + col + 1]     = acc[mt][nt][1] + b1;
                C[(size_t)(row0+8)*N + col]     = acc[mt][nt][2] + b0;
                C[(size_t)(row0+8)*N + col + 1] = acc[mt][nt][3] + b1;
            }
        }
    } else {
        __nv_bfloat16* D = (__nv_bfloat16*)Cv;
        float sc = (mode == 1) ? 0.125f : 1.0f;
        #pragma unroll
        for (int mt = 0; mt < 4; mt++) {
            int row0 = m0 + wm*64 + mt*16 + g;
            #pragma unroll
            for (int nt = 0; nt < 4; nt++) {
                int col = n0 + wn*32 + nt*8 + 2*t;
                float b0 = bias[col], b1 = bias[col+1];
                #pragma unroll
                for (int half = 0; half < 2; half++) {
                    int row = row0 + half*8;
                    int bb = row >> 11, s = row & 2047;
                    int hh = col >> 6, hd = col & 63;
                    size_t base = ((size_t)(bb*HH + hh)*SQ + s)*192;
                    float v0 = (acc[mt][nt][half*2]     + b0) * sc;
                    float v1 = (acc[mt][nt][half*2 + 1] + b1) * sc;
                    __nv_bfloat16 h0 = __float2bfloat16(v0);
                    __nv_bfloat16 l0 = __float2bfloat16(v0 - __bfloat162float(h0));
                    __nv_bfloat16 h1 = __float2bfloat16(v1);
                    __nv_bfloat16 l1 = __float2bfloat16(v1 - __bfloat162float(h1));
                    if (mode == 1) {
                        D[base + hd] = h0;       D[base + hd + 1] = h1;
                        D[base + 64 + hd] = h0;  D[base + 64 + hd + 1] = h1;
                        D[base + 128 + hd] = l0; D[base + 128 + hd + 1] = l1;
                    } else {
                        D[base + hd] = h0;       D[base + hd + 1] = h1;
                        D[base + 64 + hd] = l0;  D[base + 64 + hd + 1] = l1;
                        D[base + 128 + hd] = h0; D[base + 128 + hd + 1] = h1;
                    }
                }
            }
        }
    }
}

// ---------------------------------------------------------------------------
// HMMA flash attention v2: 3 syncs/chunk, K prefetch via cp.async,
// V-load latency hidden behind S MMAs, PV rows matched to S rows so the
// rescale factors live in registers (no arow, no lrow barrier).
// Both S and PV warp grids are 4x2: wm=w>>1 (rows 16*wm), wn=w&1.
// ---------------------------------------------------------------------------
#define QST 100
#define VST 52

__global__ __launch_bounds__(256) void attn_mma()
{
    __shared__ __align__(16) uint32_t U[6656];     // Q3s / V3s(3328)+P3s(3328)
    __shared__ __align__(16) uint32_t K3s[32*QST];
    __shared__ float mrow[64], lrow[64];
    __shared__ float pmax[64][2], psum[64][2];

    int tid = threadIdx.x, lane = tid & 31, w = tid >> 5;
    int g = lane >> 2, t = lane & 3;
    int q0 = blockIdx.x * 64;
    int bh = blockIdx.z * HH + blockIdx.y;

    int wm = w >> 1, wn = w & 1;            // shared by S and PV phases
    int r0 = wm*16 + g, r1 = r0 + 8;

    // --- Q3 tile -> persistent A-fragments ---
    const __nv_bfloat16* Qg = g_q3 + ((size_t)bh*SQ + q0)*192;
    #pragma unroll
    for (int i = 0; i < 6; i++) {
        int idx = tid + i*256;
        int r = idx / 24, c = idx % 24;
        *(uint4*)&U[r*QST + c*4] = *(const uint4*)(Qg + (size_t)r*192 + c*8);
    }
    if (tid < 64) { mrow[tid] = -INFINITY; lrow[tid] = 0.f; }
    __syncthreads();

    uint32_t qa[12][4];
    #pragma unroll
    for (int ks = 0; ks < 12; ks++) {
        int ar = (wm*16 + g)*QST + ks*8 + t;
        qa[ks][0] = U[ar];
        qa[ks][1] = U[ar + 8*QST];
        qa[ks][2] = U[ar + 4];
        qa[ks][3] = U[ar + 8*QST + 4];
    }
    __syncthreads();

    uint32_t* V3s = U;
    uint32_t* P3s = U + 3328;
    __nv_bfloat16* P3h = (__nv_bfloat16*)P3s;

    float o[4][4] = {};   // [nt][0,1]=row r0 cols, [2,3]=row r1

    const __nv_bfloat16* Kg = g_k3 + (size_t)bh*SQ*192;
    const __nv_bfloat16* Vg = g_v3t + (size_t)bh*HD*3*SQ;

    uint32_t sK = (uint32_t)__cvta_generic_to_shared(K3s);
    // K load mapping (3 x 16B per thread)
    int ki[3], kr[3], kc[3];
    #pragma unroll
    for (int i = 0; i < 3; i++) {
        ki[i] = tid + i*256;
        kr[i] = ki[i] / 24;
        kc[i] = ki[i] % 24;
    }
    // V load mapping
    int vr[3], vblk[3], vc[3];
    #pragma unroll
    for (int i = 0; i < 3; i++) {
        int idx = tid + i*256;
        vr[i] = idx / 12;
        int sub = idx % 12;
        vblk[i] = sub >> 2;
        vc[i] = sub & 3;
    }

    // prologue: cp.async K(0)
    #pragma unroll
    for (int i = 0; i < 3; i++)
        asm volatile("cp.async.cg.shared.global [%0], [%1], 16;\n"
                     :: "r"(sK + (kr[i]*QST + kc[i]*4)*4),
                        "l"(Kg + (size_t)kr[i]*192 + kc[i]*8));
    asm volatile("cp.async.commit_group;\n");

    for (int k0 = 0; k0 < SQ; k0 += 32) {
        asm volatile("cp.async.wait_group 0;\n");
        __syncthreads();   // K(c) visible; V3s/P3s free (prior PV done)

        // V global loads into registers (latency hidden behind S MMAs)
        uint4 vreg[3];
        #pragma unroll
        for (int i = 0; i < 3; i++)
            vreg[i] = *(const uint4*)(Vg + (size_t)vr[i]*3*SQ + vblk[i]*SQ + k0 + vc[i]*8);

        // --- S = Q3 @ K3^T ---
        float sc[2][4];
        #pragma unroll
        for (int nt = 0; nt < 2; nt++)
            #pragma unroll
            for (int r = 0; r < 4; r++) sc[nt][r] = 0.f;
        #pragma unroll
        for (int ks = 0; ks < 12; ks++) {
            uint32_t bfr[2][2];
            #pragma unroll
            for (int nt = 0; nt < 2; nt++) {
                int br = (wn*16 + nt*8 + g)*QST + ks*8 + t;
                bfr[nt][0] = K3s[br];
                bfr[nt][1] = K3s[br + 4];
            }
            #pragma unroll
            for (int nt = 0; nt < 2; nt++) {
                asm volatile(
                    "mma.sync.aligned.m16n8k16.row.col.f32.bf16.bf16.f32 "
                    "{%0,%1,%2,%3}, {%4,%5,%6,%7}, {%8,%9}, {%0,%1,%2,%3};"
                    : "+f"(sc[nt][0]), "+f"(sc[nt][1]), "+f"(sc[nt][2]), "+f"(sc[nt][3])
                    : "r"(qa[ks][0]), "r"(qa[ks][1]), "r"(qa[ks][2]), "r"(qa[ks][3]),
                      "r"(bfr[nt][0]), "r"(bfr[nt][1]));
            }
        }

        // V registers -> smem (consumed after sync_A)
        #pragma unroll
        for (int i = 0; i < 3; i++)
            *(uint4*)&V3s[vr[i]*VST + vblk[i]*16 + vc[i]*4] = vreg[i];

        // phase A: partial row max
        float mx0 = fmaxf(fmaxf(sc[0][0], sc[0][1]), fmaxf(sc[1][0], sc[1][1]));
        float mx1 = fmaxf(fmaxf(sc[0][2], sc[0][3]), fmaxf(sc[1][2], sc[1][3]));
        mx0 = fmaxf(mx0, __shfl_xor_sync(0xFFFFFFFFu, mx0, 1));
        mx0 = fmaxf(mx0, __shfl_xor_sync(0xFFFFFFFFu, mx0, 2));
        mx1 = fmaxf(mx1, __shfl_xor_sync(0xFFFFFFFFu, mx1, 1));
        mx1 = fmaxf(mx1, __shfl_xor_sync(0xFFFFFFFFu, mx1, 2));
        if (t == 0) { pmax[r0][wn] = mx0; pmax[r1][wn] = mx1; }
        __syncthreads();   // sync_A

        // K3s now dead: prefetch K(c+1)
        if (k0 + 32 < SQ) {
            #pragma unroll
            for (int i = 0; i < 3; i++)
                asm volatile("cp.async.cg.shared.global [%0], [%1], 16;\n"
                             :: "r"(sK + (kr[i]*QST + kc[i]*4)*4),
                                "l"(Kg + (size_t)(k0 + 32 + kr[i])*192 + kc[i]*8));
            asm volatile("cp.async.commit_group;\n");
        }

        // phase B: row max, exp, split-P writes, partial sums; capture
        // al/lold/M in registers for this warp's own rows.
        float mold0 = mrow[r0], mold1 = mrow[r1];
        float lold0 = lrow[r0], lold1 = lrow[r1];
        float M0 = fmaxf(fmaxf(pmax[r0][0], pmax[r0][1]), mold0);
        float M1 = fmaxf(fmaxf(pmax[r1][0], pmax[r1][1]), mold1);
        float al0 = __expf(mold0 - M0);
        float al1 = __expf(mold1 - M1);
        float s0 = 0.f, s1 = 0.f;
        #pragma unroll
        for (int nt = 0; nt < 2; nt++) {
            float p0 = __expf(sc[nt][0] - M0);
            float p1 = __expf(sc[nt][1] - M0);
            float p2 = __expf(sc[nt][2] - M1);
            float p3 = __expf(sc[nt][3] - M1);
            s0 += p0 + p1; s1 += p2 + p3;
            int c = wn*16 + nt*8 + 2*t;
            __nv_bfloat16 h0 = __float2bfloat16(p0);
            __nv_bfloat16 l0 = __float2bfloat16(p0 - __bfloat162float(h0));
            __nv_bfloat16 h1 = __float2bfloat16(p1);
            __nv_bfloat16 l1 = __float2bfloat16(p1 - __bfloat162float(h1));
            __nv_bfloat16 h2 = __float2bfloat16(p2);
            __nv_bfloat16 l2 = __float2bfloat16(p2 - __bfloat162float(h2));
            __nv_bfloat16 h3 = __float2bfloat16(p3);
            __nv_bfloat16 l3 = __float2bfloat16(p3 - __bfloat162float(h3));
            P3h[r0*104 + c]      = h0;  P3h[r0*104 + c + 1]      = h1;
            P3h[r0*104 + 32 + c] = h0;  P3h[r0*104 + 32 + c + 1] = h1;
            P3h[r0*104 + 64 + c] = l0;  P3h[r0*104 + 64 + c + 1] = l1;
            P3h[r1*104 + c]      = h2;  P3h[r1*104 + c + 1]      = h3;
            P3h[r1*104 + 32 + c] = h2;  P3h[r1*104 + 32 + c + 1] = h3;
            P3h[r1*104 + 64 + c] = l2;  P3h[r1*104 + 64 + c + 1] = l3;
        }
        s0 += __shfl_xor_sync(0xFFFFFFFFu, s0, 1);
        s0 += __shfl_xor_sync(0xFFFFFFFFu, s0, 2);
        s1 += __shfl_xor_sync(0xFFFFFFFFu, s1, 1);
        s1 += __shfl_xor_sync(0xFFFFFFFFu, s1, 2);
        if (t == 0) { psum[r0][wn] = s0; psum[r1][wn] = s1; }
        __syncthreads();   // sync_B (pmax/psum/P3h/V3s all visible)

        // write-only lrow/mrow update (no race: all inputs in registers/smem-read-free)
        if (wn == 0 && t == 0) {
            lrow[r0] = lold0*al0 + psum[r0][0] + psum[r0][1];
            lrow[r1] = lold1*al1 + psum[r1][0] + psum[r1][1];
            mrow[r0] = M0;
            mrow[r1] = M1;
        }

        // --- O += P3 @ V3^T (rows r0/r1, hd cols 32*wn..+31) ---
        #pragma unroll
        for (int nt = 0; nt < 4; nt++) {
            o[nt][0] *= al0; o[nt][1] *= al0;
            o[nt][2] *= al1; o[nt][3] *= al1;
        }
        #pragma unroll
        for (int ks = 0; ks < 6; ks++) {
            uint32_t pa[4], vb[4][2];
            int ar = (wm*16 + g)*VST + ks*8 + t;
            pa[0] = P3s[ar];
            pa[1] = P3s[ar + 8*VST];
            pa[2] = P3s[ar + 4];
            pa[3] = P3s[ar + 8*VST + 4];
            #pragma unroll
            for (int nt = 0; nt < 4; nt++) {
                int br = (wn*32 + nt*8 + g)*VST + ks*8 + t;
                vb[nt][0] = V3s[br];
                vb[nt][1] = V3s[br + 4];
            }
            #pragma unroll
            for (int nt = 0; nt < 4; nt++) {
                asm volatile(
                    "mma.sync.aligned.m16n8k16.row.col.f32.bf16.bf16.f32 "
                    "{%0,%1,%2,%3}, {%4,%5,%6,%7}, {%8,%9}, {%0,%1,%2,%3};"
                    : "+f"(o[nt][0]), "+f"(o[nt][1]), "+f"(o[nt][2]), "+f"(o[nt][3])
                    : "r"(pa[0]), "r"(pa[1]), "r"(pa[2]), "r"(pa[3]),
                      "r"(vb[nt][0]), "r"(vb[nt][1]));
            }
        }
        // no loop-end sync: next iteration's top sync covers V3s/P3s reuse
    }

    __syncthreads();   // final lrow writes visible

    // epilogue: normalize + split-write g_o3 ([h|h|l] over DM)
    int b = blockIdx.z, h = blockIdx.y;
    float i0 = 1.f / lrow[r0];
    float i1 = 1.f / lrow[r1];
    size_t b0 = (size_t)(b*SQ + q0 + r0)*K3;
    size_t b1 = (size_t)(b*SQ + q0 + r1)*K3;
    #pragma unroll
    for (int nt = 0; nt < 4; nt++) {
        int col = h*64 + wn*32 + nt*8 + 2*t;
        float v00 = o[nt][0] * i0, v01 = o[nt][1] * i0;
        float v10 = o[nt][2] * i1, v11 = o[nt][3] * i1;
        __nv_bfloat16 h00 = __float2bfloat16(v00);
        __nv_bfloat16 l00 = __float2bfloat16(v00 - __bfloat162float(h00));
        __nv_bfloat16 h01 = __float2bfloat16(v01);
        __nv_bfloat16 l01 = __float2bfloat16(v01 - __bfloat162float(h01));
        __nv_bfloat16 h10 = __float2bfloat16(v10);
        __nv_bfloat16 l10 = __float2bfloat16(v10 - __bfloat162float(h10));
        __nv_bfloat16 h11 = __float2bfloat16(v11);
        __nv_bfloat16 l11 = __float2bfloat16(v11 - __bfloat162float(h11));
        g_o3[b0 + col] = h00;          g_o3[b0 + col + 1] = h01;
        g_o3[b0 + DM + col] = h00;     g_o3[b0 + DM + col + 1] = h01;
        g_o3[b0 + 2*DM + col] = l00;   g_o3[b0 + 2*DM + col + 1] = l01;
        g_o3[b1 + col] = h10;          g_o3[b1 + col + 1] = h11;
        g_o3[b1 + DM + col] = h10;     g_o3[b1 + DM + col + 1] = h11;
        g_o3[b1 + 2*DM + col] = l10;   g_o3[b1 + 2*DM + col + 1] = l11;
    }
}

extern "C" void kernel_launch(void* const* d_in, const int* in_sizes, int n_in,
                              void* d_out, int out_size)
{
    const float* x  = (const float*)d_in[0];
    const float* wq = (const float*)d_in[1];
    const float* bq = (const float*)d_in[2];
    const float* wk = (const float*)d_in[3];
    const float* bk = (const float*)d_in[4];
    const float* wv = (const float*)d_in[5];
    const float* bv = (const float*)d_in[6];
    const float* wo = (const float*)d_in[7];
    const float* bo = (const float*)d_in[8];
    float* out = (float*)d_out;

    float *v;
    __nv_bfloat16 *x3, *o3, *wq3, *wk3, *wv3, *wo3, *q3, *k3;
    cudaGetSymbolAddress((void**)&v, g_v);
    cudaGetSymbolAddress((void**)&x3, g_x3);
    cudaGetSymbolAddress((void**)&o3, g_o3);
    cudaGetSymbolAddress((void**)&wq3, g_wq3);
    cudaGetSymbolAddress((void**)&wk3, g_wk3);
    cudaGetSymbolAddress((void**)&wv3, g_wv3);
    cudaGetSymbolAddress((void**)&wo3, g_wo3);
    cudaGetSymbolAddress((void**)&q3, g_q3);
    cudaGetSymbolAddress((void**)&k3, g_k3);

    int eb = (MR*DM + 255)/256;
    dim3 tb(DM/32, DM/32);
    dim3 gg(DM/128, MR/128);

    expand_a3<<<eb, 256>>>(x, x3, MR, DM);
    expand_b3t<<<tb, 256>>>(wq, wq3, DM, DM);
    expand_b3t<<<tb, 256>>>(wk, wk3, DM, DM);
    expand_b3t<<<tb, 256>>>(wv, wv3, DM, DM);
    gemm_bf16<<<gg, 256>>>(x3, wq3, bq, q3, MR, DM, K3, 1);
    gemm_bf16<<<gg, 256>>>(x3, wk3, bk, k3, MR, DM, K3, 2);
    gemm_bf16<<<gg, 256>>>(x3, wv3, bv, v,  MR, DM, K3, 0);

    expand_v3t<<<dim3(SQ/32, HD/32, BZ*HH), 256>>>(v);

    attn_mma<<<dim3(SQ/64, HH, BZ), 256>>>();

    expand_b3t<<<tb, 256>>>(wo, wo3, DM, DM);
    gemm_bf16<<<gg, 256>>>(o3, wo3, bo, out, MR, DM, K3, 0);
}